// round 12
// baseline (speedup 1.0000x reference)
#include <cuda_runtime.h>
#include <cstdint>
#include <math.h>

// Problem constants (fixed shapes per reference)
#define BB   2
#define SS   4096
#define DD   512
#define HH   8
#define DHH  64
#define MM   (BB*SS)      // 8192 rows

// ---------------- scratch (device globals; no allocations allowed) ----------
__device__ uint16_t g_qkvbf[MM * 1536];         // bf16 qkv (attention input)
__device__ float    g_r1 [MM * DD];             // pre-LN buffer (reused)
__device__ float    g_h  [MM * DD];             // LN1 out fp32 (MLP residual)
__device__ uint32_t g_xbf   [MM * DD / 2];      // bf16x2 shadows
__device__ uint32_t g_ctxbf [MM * DD / 2];
__device__ uint32_t g_hbf   [MM * DD / 2];
__device__ uint32_t g_midbf [MM * DD / 2];
__device__ uint32_t g_winbf [1536 * DD / 2];
__device__ uint32_t g_woutbf[DD * DD / 2];
__device__ uint32_t g_w1bf  [DD * DD / 2];
__device__ uint32_t g_w2bf  [DD * DD / 2];

// ---------------- helpers ----------------------------------------------------
__device__ __forceinline__ uint32_t bfpack(float lo, float hi) {
    uint32_t r; asm("cvt.rn.bf16x2.f32 %0, %1, %2;" : "=r"(r) : "f"(hi), "f"(lo)); return r;
}
__device__ __forceinline__ void mma_bf16(float* d, const uint32_t* a, const uint32_t* b) {
    asm volatile(
        "mma.sync.aligned.m16n8k16.row.col.f32.bf16.bf16.f32 "
        "{%0,%1,%2,%3}, {%4,%5,%6,%7}, {%8,%9}, {%0,%1,%2,%3};"
        : "+f"(d[0]), "+f"(d[1]), "+f"(d[2]), "+f"(d[3])
        : "r"(a[0]), "r"(a[1]), "r"(a[2]), "r"(a[3]),
          "r"(b[0]), "r"(b[1]));
}
__device__ __forceinline__ void ldsm_x4(uint32_t* r, uint32_t addr) {
    asm volatile("ldmatrix.sync.aligned.m8n8.x4.shared.b16 {%0,%1,%2,%3}, [%4];"
        : "=r"(r[0]), "=r"(r[1]), "=r"(r[2]), "=r"(r[3]) : "r"(addr));
}
__device__ __forceinline__ void ldsm_x4t(uint32_t* r, uint32_t addr) {
    asm volatile("ldmatrix.sync.aligned.m8n8.x4.trans.shared.b16 {%0,%1,%2,%3}, [%4];"
        : "=r"(r[0]), "=r"(r[1]), "=r"(r[2]), "=r"(r[3]) : "r"(addr));
}
// GEMM staging: .cg (L2 only).  Attention staging: .ca (keep L1 reuse).
__device__ __forceinline__ void cpa16cg(uint32_t d, const void* s) {
    asm volatile("cp.async.cg.shared.global [%0], [%1], 16;" :: "r"(d), "l"(s));
}
__device__ __forceinline__ void cpa16ca(uint32_t d, const void* s) {
    asm volatile("cp.async.ca.shared.global [%0], [%1], 16;" :: "r"(d), "l"(s));
}
__device__ __forceinline__ void cpa16za(uint32_t d, const void* s, int sz) {
    asm volatile("cp.async.ca.shared.global [%0], [%1], 16, %2;" :: "r"(d), "l"(s), "r"(sz));
}
__device__ __forceinline__ void cpa_commit() { asm volatile("cp.async.commit_group;" ::: "memory"); }
__device__ __forceinline__ void cpa_wait1()  { asm volatile("cp.async.wait_group 1;" ::: "memory"); }
__device__ __forceinline__ void cpa_wait0()  { asm volatile("cp.async.wait_group 0;" ::: "memory"); }

// ---------------- fused fp32 -> bf16x2 conversion (all 5 tensors) -----------
#define CVT_N0 1048576
#define CVT_N1 (CVT_N0 + 196608)
#define CVT_N2 (CVT_N1 + 65536)
#define CVT_N3 (CVT_N2 + 65536)
#define CVT_TOT (CVT_N3 + 65536)

__global__ __launch_bounds__(256)
void cvtbf_all(const float* __restrict__ x,    const float* __restrict__ win,
               const float* __restrict__ wout, const float* __restrict__ w1,
               const float* __restrict__ w2,
               uint32_t* __restrict__ xbf,    uint32_t* __restrict__ winbf,
               uint32_t* __restrict__ woutbf, uint32_t* __restrict__ w1bf,
               uint32_t* __restrict__ w2bf)
{
    const int i = blockIdx.x * 256 + threadIdx.x;
    const float* src; uint32_t* dst; int j;
    if (i < CVT_N0)      { src = x;    dst = xbf;    j = i; }
    else if (i < CVT_N1) { src = win;  dst = winbf;  j = i - CVT_N0; }
    else if (i < CVT_N2) { src = wout; dst = woutbf; j = i - CVT_N1; }
    else if (i < CVT_N3) { src = w1;   dst = w1bf;   j = i - CVT_N2; }
    else                 { src = w2;   dst = w2bf;   j = i - CVT_N3; }
    float4 v = ((const float4*)src)[j];
    uint2 p;
    p.x = bfpack(v.x, v.y);
    p.y = bfpack(v.z, v.w);
    ((uint2*)dst)[j] = p;
}

// ========== bf16 mma GEMM: 64x64 CTA tile, ONE warp, no barriers =============
// C = A @ W^T + bias (+epilogue). A:[M,K] bf16, W:[N,K] bf16. K mult of 32.
// Single-warp CTA -> fully independent warps, cp.async 3-slab ring, syncwarp only.
// MODE 1: fp32 +bias+resid; MODE 2: bf16 +bias+relu; MODE 3: bf16 +bias
#define GST    40                  // smem row stride (bf16 elems)
#define GSLOT  (64*GST)            // per-matrix per-stage elems (2560)

template<int MODE>
__global__ __launch_bounds__(32)
void gemm_bf(const uint32_t* __restrict__ Abf, const uint32_t* __restrict__ Wbf,
             const float* __restrict__ bias, const float* __restrict__ resid,
             void* __restrict__ Cout, int M, int N, int K)
{
    __shared__ __align__(16) uint16_t gsm[6 * GSLOT];   // 30720 bytes
    uint16_t* As = gsm;                 // [3][64][40]
    uint16_t* Ws = gsm + 3 * GSLOT;

    const int lane = threadIdx.x;
    const int grp  = lane >> 2;
    const int tig  = lane & 3;
    const int brow = blockIdx.y * 64;
    const int bcol = blockIdx.x * 64;

    // staging: lane loads rows 2*lane, 2*lane+1 of both matrices
    const uint16_t* gA = (const uint16_t*)Abf + (size_t)(brow + 2 * lane) * K;
    const uint16_t* gB = (const uint16_t*)Wbf + (size_t)(bcol + 2 * lane) * K;
    const uint32_t sA = (uint32_t)__cvta_generic_to_shared(As + 2 * lane * GST);
    const uint32_t sB = (uint32_t)__cvta_generic_to_shared(Ws + 2 * lane * GST);

    const uint32_t sm0 = (uint32_t)__cvta_generic_to_shared(gsm);
    uint32_t aoff[4], boff[4];
#pragma unroll
    for (int mt = 0; mt < 4; mt++)
        aoff[mt] = ((mt * 16 + (lane & 15)) * GST + ((lane >> 4) & 1) * 8) * 2;
#pragma unroll
    for (int p = 0; p < 4; p++)
        boff[p] = ((16 * p + (lane & 7) + ((lane >> 4) & 1) * 8) * GST
                   + ((lane >> 3) & 1) * 8) * 2 + 3 * GSLOT * 2;

    const int NS = K >> 5;

#define GPREF(s) do { \
        const uint32_t _o = ((s) % 3) * (GSLOT * 2); \
        const uint16_t* _ga = gA + (s) * 32; \
        const uint16_t* _gb = gB + (s) * 32; \
        cpa16cg(sA + _o,      _ga);      cpa16cg(sA + _o + 16, _ga + 8); \
        cpa16cg(sA + _o + 32, _ga + 16); cpa16cg(sA + _o + 48, _ga + 24); \
        cpa16cg(sA + _o + 80, _ga + K);      cpa16cg(sA + _o + 96,  _ga + K + 8); \
        cpa16cg(sA + _o + 112, _ga + K + 16); cpa16cg(sA + _o + 128, _ga + K + 24); \
        cpa16cg(sB + _o,      _gb);      cpa16cg(sB + _o + 16, _gb + 8); \
        cpa16cg(sB + _o + 32, _gb + 16); cpa16cg(sB + _o + 48, _gb + 24); \
        cpa16cg(sB + _o + 80, _gb + K);      cpa16cg(sB + _o + 96,  _gb + K + 8); \
        cpa16cg(sB + _o + 112, _gb + K + 16); cpa16cg(sB + _o + 128, _gb + K + 24); \
        cpa_commit(); \
    } while (0)

    GPREF(0);
    GPREF(1);

    float acc[4][8][4];
#pragma unroll
    for (int mt = 0; mt < 4; mt++)
#pragma unroll
        for (int nt = 0; nt < 8; nt++)
#pragma unroll
            for (int r = 0; r < 4; r++) acc[mt][nt][r] = 0.f;

    for (int s = 0; s < NS; s++) {
        if (s == NS - 1) cpa_wait0(); else cpa_wait1();
        __syncwarp();
        if (s + 2 < NS) GPREF(s + 2);

        const uint32_t stg = sm0 + (s % 3) * (GSLOT * 2);
#pragma unroll
        for (int ks = 0; ks < 2; ks++) {
            const uint32_t kb = stg + ks * 32;
            uint32_t afr[4][4];
#pragma unroll
            for (int mt = 0; mt < 4; mt++) ldsm_x4(afr[mt], kb + aoff[mt]);
            uint32_t bfr[4][4];
#pragma unroll
            for (int p = 0; p < 4; p++)  ldsm_x4(bfr[p], kb + boff[p]);
#pragma unroll
            for (int mt = 0; mt < 4; mt++)
#pragma unroll
                for (int p = 0; p < 4; p++) {
                    mma_bf16(acc[mt][2*p  ], afr[mt], &bfr[p][0]);
                    mma_bf16(acc[mt][2*p+1], afr[mt], &bfr[p][2]);
                }
        }
        __syncwarp();   // all lanes done reading this slab before it refills
    }

    // epilogue
#pragma unroll
    for (int mt = 0; mt < 4; mt++) {
#pragma unroll
        for (int half = 0; half < 2; half++) {
            const int grow = brow + 16 * mt + grp + 8 * half;
            const float* rrow = (MODE == 1) ? (resid + (size_t)grow * N + bcol) : nullptr;
#pragma unroll
            for (int nt = 0; nt < 8; nt++) {
                const int col = 8 * nt + 2 * tig;
                float ox = acc[mt][nt][2 * half + 0] + bias[bcol + col];
                float oy = acc[mt][nt][2 * half + 1] + bias[bcol + col + 1];
                if (MODE == 1) {
                    const float2 rv = *(const float2*)(rrow + col);
                    ox += rv.x; oy += rv.y;
                    float2 o; o.x = ox; o.y = oy;
                    *(float2*)((float*)Cout + (size_t)grow * N + bcol + col) = o;
                } else {
                    if (MODE == 2) { ox = fmaxf(ox, 0.f); oy = fmaxf(oy, 0.f); }
                    ((uint32_t*)Cout)[((size_t)grow * N + bcol + col) >> 1] = bfpack(ox, oy);
                }
            }
        }
    }
}

// ============ sliding-window flash attention, full bf16 mma ==================
// Q tile 64 rows, 4 warps (16 rows each). P stays in registers (C->A repack).
// K B-frags: plain ldmatrix; V B-frags: ldmatrix.trans. Stride 72 conflict-free.
#define QK_STR 72
#define KVBUF  (64 * QK_STR)     // uint16 elems per buffer

__global__ __launch_bounds__(128)
void attn_bf(const uint16_t* __restrict__ qkv, uint32_t* __restrict__ ctxbf,
             const int* __restrict__ wptr)
{
    __shared__ __align__(16) uint16_t Qs[KVBUF];
    __shared__ __align__(16) uint16_t Ks[2][KVBUF];
    __shared__ __align__(16) uint16_t Vs[2][KVBUF];

    int w = *wptr;
    if (w < 0 || w > 1000000) w = (int)__int_as_float((unsigned)w);

    const int t    = threadIdx.x;
    const int warp = t >> 5;
    const int lane = t & 31;
    const int grp  = lane >> 2;
    const int tig  = lane & 3;
    const int wm   = warp * 16;
    const int q0   = blockIdx.x * 64;
    const int h    = blockIdx.y;
    const int b    = blockIdx.z;

    const uint32_t qsb = (uint32_t)__cvta_generic_to_shared(Qs);
    const uint32_t ksb = (uint32_t)__cvta_generic_to_shared(Ks);
    const uint32_t vsb = (uint32_t)__cvta_generic_to_shared(Vs);

    int j0s = q0 - w; if (j0s < 0) j0s = 0; j0s &= ~63;
    int jend = q0 + 64 + w; if (jend > SS) jend = SS;
    const int ntl = (jend - j0s + 63) >> 6;

    const int pr  = t & 63;
    const int isV = t >> 6;
#define APREF(ti, buf) do { \
        const int _jr = j0s + (ti) * 64 + pr; \
        const int _sz = (_jr < SS) ? 16 : 0; \
        const int _jc = (_jr < SS) ? _jr : (SS - 1); \
        const uint16_t* _src = qkv + ((size_t)(b * SS + _jc)) * 1536 + 512 + isV * 512 + h * 64; \
        const uint32_t _dst = (isV ? vsb : ksb) + (buf) * (KVBUF * 2) + pr * (QK_STR * 2); \
        _Pragma("unroll") \
        for (int _ci = 0; _ci < 8; _ci++) cpa16za(_dst + 16 * _ci, _src + 8 * _ci, _sz); \
        cpa_commit(); \
    } while (0)

    // stage Q (cp.async) + start tile-0 prefetch
    {
        const int qr = t >> 1, qh = (t & 1) * 32;
        const uint16_t* qp = qkv + ((size_t)(b * SS + q0 + qr)) * 1536 + h * 64 + qh;
        const uint32_t qd = qsb + (qr * QK_STR + qh) * 2;
#pragma unroll
        for (int i = 0; i < 4; i++) cpa16ca(qd + 16 * i, qp + 8 * i);
    }
    APREF(0, 0);
    cpa_wait0();
    __syncthreads();

    // Q A-fragments (registers, reused across all tiles)
    uint32_t aq[4][4];
#pragma unroll
    for (int kt = 0; kt < 4; kt++)
        ldsm_x4(aq[kt], qsb + ((wm + (lane & 15)) * QK_STR + kt * 16 + ((lane >> 4) & 1) * 8) * 2);

    uint32_t koff[4], voff[4];
#pragma unroll
    for (int p = 0; p < 4; p++) {
        koff[p] = ((16 * p + (lane & 7) + ((lane >> 4) & 1) * 8) * QK_STR
                   + ((lane >> 3) & 1) * 8) * 2;
        voff[p] = (((lane & 7) + ((lane >> 3) & 1) * 8) * QK_STR
                   + p * 16 + ((lane >> 4) & 1) * 8) * 2;
    }

    float oc[8][4];
#pragma unroll
    for (int nt = 0; nt < 8; nt++) { oc[nt][0]=0.f; oc[nt][1]=0.f; oc[nt][2]=0.f; oc[nt][3]=0.f; }
    float m0 = -1e30f, m1 = -1e30f, l0 = 0.f, l1 = 0.f;
    const int qg0 = q0 + wm + grp, qg1 = qg0 + 8;

    for (int ti = 0; ti < ntl; ti++) {
        if (ti + 1 < ntl) { APREF(ti + 1, (ti + 1) & 1); cpa_wait1(); }
        else              { cpa_wait0(); }
        __syncthreads();

        const uint32_t kbase = ksb + (ti & 1) * (KVBUF * 2);
        const uint32_t vbase = vsb + (ti & 1) * (KVBUF * 2);
        const int j0 = j0s + ti * 64;

        // ---- S = Q @ K^T (bf16) ------------------------------------------
        float sc[8][4];
#pragma unroll
        for (int nt = 0; nt < 8; nt++) { sc[nt][0]=0.f; sc[nt][1]=0.f; sc[nt][2]=0.f; sc[nt][3]=0.f; }
#pragma unroll
        for (int kd = 0; kd < 4; kd++) {
#pragma unroll
            for (int p = 0; p < 4; p++) {
                uint32_t bq[4];
                ldsm_x4(bq, kbase + koff[p] + kd * 32);
                mma_bf16(sc[2*p  ], aq[kd], &bq[0]);
                mma_bf16(sc[2*p+1], aq[kd], &bq[2]);
            }
        }

        // ---- scale + mask + online softmax -------------------------------
        float tm0 = -1e30f, tm1 = -1e30f;
#pragma unroll
        for (int nt = 0; nt < 8; nt++) {
            sc[nt][0] *= 0.125f; sc[nt][1] *= 0.125f;
            sc[nt][2] *= 0.125f; sc[nt][3] *= 0.125f;
            const int ja = j0 + 8 * nt + 2 * tig;
            const int jb = ja + 1;
            if (ja >= SS || abs(qg0 - ja) > w) sc[nt][0] = -1e30f;
            if (jb >= SS || abs(qg0 - jb) > w) sc[nt][1] = -1e30f;
            if (ja >= SS || abs(qg1 - ja) > w) sc[nt][2] = -1e30f;
            if (jb >= SS || abs(qg1 - jb) > w) sc[nt][3] = -1e30f;
            tm0 = fmaxf(tm0, fmaxf(sc[nt][0], sc[nt][1]));
            tm1 = fmaxf(tm1, fmaxf(sc[nt][2], sc[nt][3]));
        }
        tm0 = fmaxf(tm0, __shfl_xor_sync(0xffffffffu, tm0, 1));
        tm0 = fmaxf(tm0, __shfl_xor_sync(0xffffffffu, tm0, 2));
        tm1 = fmaxf(tm1, __shfl_xor_sync(0xffffffffu, tm1, 1));
        tm1 = fmaxf(tm1, __shfl_xor_sync(0xffffffffu, tm1, 2));
        const float mn0 = fmaxf(m0, tm0), mn1 = fmaxf(m1, tm1);
        const float cf0 = __expf(m0 - mn0), cf1 = __expf(m1 - mn1);
        l0 *= cf0; l1 *= cf1;
#pragma unroll
        for (int nt = 0; nt < 8; nt++) {
            oc[nt][0] *= cf0; oc[nt][1] *= cf0;
            oc[nt][2] *= cf1; oc[nt][3] *= cf1;
        }
        float rs0 = 0.f, rs1 = 0.f;
#pragma unroll
        for (int nt = 0; nt < 8; nt++) {
            sc[nt][0] = __expf(sc[nt][0] - mn0);
            sc[nt][1] = __expf(sc[nt][1] - mn0);
            sc[nt][2] = __expf(sc[nt][2] - mn1);
            sc[nt][3] = __expf(sc[nt][3] - mn1);
            rs0 += sc[nt][0] + sc[nt][1];
            rs1 += sc[nt][2] + sc[nt][3];
        }
        rs0 += __shfl_xor_sync(0xffffffffu, rs0, 1);
        rs0 += __shfl_xor_sync(0xffffffffu, rs0, 2);
        rs1 += __shfl_xor_sync(0xffffffffu, rs1, 1);
        rs1 += __shfl_xor_sync(0xffffffffu, rs1, 2);
        l0 += rs0; l1 += rs1;
        m0 = mn0; m1 = mn1;

        // ---- P C-frags -> A-frags entirely in registers ------------------
        uint32_t ap[4][4];
#pragma unroll
        for (int jt = 0; jt < 4; jt++) {
            ap[jt][0] = bfpack(sc[2*jt  ][0], sc[2*jt  ][1]);
            ap[jt][1] = bfpack(sc[2*jt  ][2], sc[2*jt  ][3]);
            ap[jt][2] = bfpack(sc[2*jt+1][0], sc[2*jt+1][1]);
            ap[jt][3] = bfpack(sc[2*jt+1][2], sc[2*jt+1][3]);
        }

        // ---- O += P @ V (V^T via ldmatrix.trans) -------------------------
#pragma unroll
        for (int jt = 0; jt < 4; jt++) {
            const uint32_t jb2 = vbase + jt * (16 * QK_STR * 2);
#pragma unroll
            for (int p = 0; p < 4; p++) {
                uint32_t bv[4];
                ldsm_x4t(bv, jb2 + voff[p]);
                mma_bf16(oc[2*p  ], ap[jt], &bv[0]);
                mma_bf16(oc[2*p+1], ap[jt], &bv[2]);
            }
        }
        __syncthreads();   // done with this K/V buffer before refill
    }

    const float inv0 = 1.f / l0, inv1 = 1.f / l1;
    uint32_t* c0p = ctxbf + (((size_t)(b * SS + qg0)) * DD + h * 64) / 2;
    uint32_t* c1p = ctxbf + (((size_t)(b * SS + qg1)) * DD + h * 64) / 2;
#pragma unroll
    for (int nt = 0; nt < 8; nt++) {
        const int d = 8 * nt + 2 * tig;
        c0p[d >> 1] = bfpack(oc[nt][0] * inv0, oc[nt][1] * inv0);
        c1p[d >> 1] = bfpack(oc[nt][2] * inv1, oc[nt][3] * inv1);
    }
}

// ---------------- LayerNorm (one block per row, D=512) ----------------------
__global__ __launch_bounds__(128)
void ln_kernel(const float* __restrict__ in, const float* __restrict__ g,
               const float* __restrict__ b, float* __restrict__ out,
               uint32_t* __restrict__ outbf)
{
    __shared__ float red[4];
    const int row = blockIdx.x;
    const int t = threadIdx.x;
    float4 v = ((const float4*)(in + (size_t)row * DD))[t];

    float s = v.x + v.y + v.z + v.w;
#pragma unroll
    for (int o1 = 16; o1; o1 >>= 1) s += __shfl_xor_sync(0xffffffffu, s, o1);
    if ((t & 31) == 0) red[t >> 5] = s;
    __syncthreads();
    const float mean = (red[0] + red[1] + red[2] + red[3]) * (1.f / 512.f);

    const float dx0 = v.x - mean, dx1 = v.y - mean, dx2 = v.z - mean, dx3 = v.w - mean;
    float sq = dx0*dx0 + dx1*dx1 + dx2*dx2 + dx3*dx3;
#pragma unroll
    for (int o1 = 16; o1; o1 >>= 1) sq += __shfl_xor_sync(0xffffffffu, sq, o1);
    __syncthreads();
    if ((t & 31) == 0) red[t >> 5] = sq;
    __syncthreads();
    const float var = (red[0] + red[1] + red[2] + red[3]) * (1.f / 512.f);
    const float rs = rsqrtf(var + 1e-5f);

    float4 gv = ((const float4*)g)[t];
    float4 bv = ((const float4*)b)[t];
    float4 ov;
    ov.x = dx0 * rs * gv.x + bv.x;
    ov.y = dx1 * rs * gv.y + bv.y;
    ov.z = dx2 * rs * gv.z + bv.z;
    ov.w = dx3 * rs * gv.w + bv.w;
    ((float4*)(out + (size_t)row * DD))[t] = ov;
    if (outbf) {
        uint2 p;
        p.x = bfpack(ov.x, ov.y);
        p.y = bfpack(ov.z, ov.w);
        ((uint2*)(outbf + (size_t)row * DD / 2))[t] = p;
    }
}

// ---------------- launch ----------------------------------------------------
extern "C" void kernel_launch(void* const* d_in, const int* in_sizes, int n_in,
                              void* d_out, int out_size)
{
    const float* x     = (const float*)d_in[0];
    const float* w_in  = (const float*)d_in[1];
    const float* b_in  = (const float*)d_in[2];
    const float* w_out = (const float*)d_in[3];
    const float* b_out = (const float*)d_in[4];
    const float* ln1g  = (const float*)d_in[5];
    const float* ln1b  = (const float*)d_in[6];
    const float* ln2g  = (const float*)d_in[7];
    const float* ln2b  = (const float*)d_in[8];
    const float* w1    = (const float*)d_in[9];
    const float* b1    = (const float*)d_in[10];
    const float* w2    = (const float*)d_in[11];
    const float* b2    = (const float*)d_in[12];
    const int*   wnd   = (const int*)d_in[13];

    float *r1, *hbuf;
    uint16_t* qkvbf;
    uint32_t *xbf, *ctxbf, *hbf, *midbf, *winbf, *woutbf, *w1bf, *w2bf;
    cudaGetSymbolAddress((void**)&qkvbf,  g_qkvbf);
    cudaGetSymbolAddress((void**)&r1,     g_r1);
    cudaGetSymbolAddress((void**)&hbuf,   g_h);
    cudaGetSymbolAddress((void**)&xbf,    g_xbf);
    cudaGetSymbolAddress((void**)&ctxbf,  g_ctxbf);
    cudaGetSymbolAddress((void**)&hbf,    g_hbf);
    cudaGetSymbolAddress((void**)&midbf,  g_midbf);
    cudaGetSymbolAddress((void**)&winbf,  g_winbf);
    cudaGetSymbolAddress((void**)&woutbf, g_woutbf);
    cudaGetSymbolAddress((void**)&w1bf,   g_w1bf);
    cudaGetSymbolAddress((void**)&w2bf,   g_w2bf);

    // 0) fused bf16 conversions (x + all weights)
    cvtbf_all<<<CVT_TOT / 256, 256>>>(x, w_in, w_out, w1, w2,
                                      xbf, winbf, woutbf, w1bf, w2bf);
    // 1) fused QKV projection -> bf16 qkv   (24 x 128 = 3072 single-warp CTAs)
    gemm_bf<3><<<dim3(24, 128), 32>>>(xbf, winbf, b_in, nullptr, qkvbf, MM, 1536, DD);
    // 2) sliding-window flash attention (bf16) -> bf16 ctx
    attn_bf<<<dim3(SS / 64, HH, BB), 128>>>(qkvbf, ctxbf, wnd);
    // 3) out_proj + residual(x) -> fp32 r1  (8 x 128 = 1024 CTAs)
    gemm_bf<1><<<dim3(8, 128), 32>>>(ctxbf, woutbf, b_out, x, r1, MM, DD, DD);
    // 4) LN1 -> fp32 h + bf16 shadow
    ln_kernel<<<MM, 128>>>(r1, ln1g, ln1b, hbuf, hbf);
    // 5) MLP fc1 + relu -> bf16 mid
    gemm_bf<2><<<dim3(8, 128), 32>>>(hbf, w1bf, b1, nullptr, midbf, MM, DD, DD);
    // 6) MLP fc2 + residual(h) -> fp32 r1
    gemm_bf<1><<<dim3(8, 128), 32>>>(midbf, w2bf, b2, hbuf, r1, MM, DD, DD);
    // 7) LN2 -> output
    ln_kernel<<<MM, 128>>>(r1, ln2g, ln2b, (float*)d_out, nullptr);
}

// round 13
// speedup vs baseline: 1.2184x; 1.2184x over previous
#include <cuda_runtime.h>
#include <cstdint>
#include <math.h>

// Problem constants (fixed shapes per reference)
#define BB   2
#define SS   4096
#define DD   512
#define HH   8
#define DHH  64
#define MM   (BB*SS)      // 8192 rows

// ---------------- scratch (device globals; no allocations allowed) ----------
__device__ uint16_t g_qkvbf[MM * 1536];         // bf16 qkv (attention input)
__device__ float    g_r1 [MM * DD];             // pre-LN buffer (reused)
__device__ float    g_h  [MM * DD];             // LN1 out fp32 (MLP residual)
__device__ uint32_t g_xbf   [MM * DD / 2];      // bf16x2 shadows
__device__ uint32_t g_ctxbf [MM * DD / 2];
__device__ uint32_t g_hbf   [MM * DD / 2];
__device__ uint32_t g_midbf [MM * DD / 2];
__device__ uint32_t g_winbf [1536 * DD / 2];
__device__ uint32_t g_woutbf[DD * DD / 2];
__device__ uint32_t g_w1bf  [DD * DD / 2];
__device__ uint32_t g_w2bf  [DD * DD / 2];

// ---------------- helpers ----------------------------------------------------
__device__ __forceinline__ uint32_t bfpack(float lo, float hi) {
    uint32_t r; asm("cvt.rn.bf16x2.f32 %0, %1, %2;" : "=r"(r) : "f"(hi), "f"(lo)); return r;
}
__device__ __forceinline__ void mma_bf16(float* d, const uint32_t* a, const uint32_t* b) {
    asm volatile(
        "mma.sync.aligned.m16n8k16.row.col.f32.bf16.bf16.f32 "
        "{%0,%1,%2,%3}, {%4,%5,%6,%7}, {%8,%9}, {%0,%1,%2,%3};"
        : "+f"(d[0]), "+f"(d[1]), "+f"(d[2]), "+f"(d[3])
        : "r"(a[0]), "r"(a[1]), "r"(a[2]), "r"(a[3]),
          "r"(b[0]), "r"(b[1]));
}
__device__ __forceinline__ void ldsm_x4(uint32_t* r, uint32_t addr) {
    asm volatile("ldmatrix.sync.aligned.m8n8.x4.shared.b16 {%0,%1,%2,%3}, [%4];"
        : "=r"(r[0]), "=r"(r[1]), "=r"(r[2]), "=r"(r[3]) : "r"(addr));
}
__device__ __forceinline__ void ldsm_x4t(uint32_t* r, uint32_t addr) {
    asm volatile("ldmatrix.sync.aligned.m8n8.x4.trans.shared.b16 {%0,%1,%2,%3}, [%4];"
        : "=r"(r[0]), "=r"(r[1]), "=r"(r[2]), "=r"(r[3]) : "r"(addr));
}
__device__ __forceinline__ void cpa16(uint32_t d, const void* s) {
    asm volatile("cp.async.ca.shared.global [%0], [%1], 16;" :: "r"(d), "l"(s));
}
__device__ __forceinline__ void cpa16z(uint32_t d, const void* s, int sz) {
    asm volatile("cp.async.ca.shared.global [%0], [%1], 16, %2;" :: "r"(d), "l"(s), "r"(sz));
}
__device__ __forceinline__ void cpa_commit() { asm volatile("cp.async.commit_group;" ::: "memory"); }
__device__ __forceinline__ void cpa_wait1()  { asm volatile("cp.async.wait_group 1;" ::: "memory"); }
__device__ __forceinline__ void cpa_wait0()  { asm volatile("cp.async.wait_group 0;" ::: "memory"); }

// ---------------- fused fp32 -> bf16x2 conversion (all 5 tensors) -----------
#define CVT_N0 1048576
#define CVT_N1 (CVT_N0 + 196608)
#define CVT_N2 (CVT_N1 + 65536)
#define CVT_N3 (CVT_N2 + 65536)
#define CVT_TOT (CVT_N3 + 65536)

__global__ __launch_bounds__(256)
void cvtbf_all(const float* __restrict__ x,    const float* __restrict__ win,
               const float* __restrict__ wout, const float* __restrict__ w1,
               const float* __restrict__ w2,
               uint32_t* __restrict__ xbf,    uint32_t* __restrict__ winbf,
               uint32_t* __restrict__ woutbf, uint32_t* __restrict__ w1bf,
               uint32_t* __restrict__ w2bf)
{
    const int i = blockIdx.x * 256 + threadIdx.x;
    const float* src; uint32_t* dst; int j;
    if (i < CVT_N0)      { src = x;    dst = xbf;    j = i; }
    else if (i < CVT_N1) { src = win;  dst = winbf;  j = i - CVT_N0; }
    else if (i < CVT_N2) { src = wout; dst = woutbf; j = i - CVT_N1; }
    else if (i < CVT_N3) { src = w1;   dst = w1bf;   j = i - CVT_N2; }
    else                 { src = w2;   dst = w2bf;   j = i - CVT_N3; }
    float4 v = ((const float4*)src)[j];
    uint2 p;
    p.x = bfpack(v.x, v.y);
    p.y = bfpack(v.z, v.w);
    ((uint2*)dst)[j] = p;
}

// ======== bf16 mma GEMM: CTA tile 64x128, 4 warps (32x64 warp tiles) =========
// C = A @ W^T + bias (+epilogue). A:[M,K] bf16, W:[N,K] bf16. K mult of 32.
// Grid doubles vs 128x128 tiles -> ~14 warps/SM (latency-bound fix).
// MODE 1: fp32 +bias+resid; MODE 2: bf16 +bias+relu; MODE 3: bf16 +bias
#define ASLAB (64*40)              // A elems per stage
#define BSLAB (128*40)             // B elems per stage
#define GEMM_SMEM_ST  (3*(ASLAB+BSLAB)*2)   // 46080 bytes (static)

template<int MODE>
__global__ __launch_bounds__(128)
void gemm_bf(const uint32_t* __restrict__ Abf, const uint32_t* __restrict__ Wbf,
             const float* __restrict__ bias, const float* __restrict__ resid,
             void* __restrict__ Cout, int M, int N, int K)
{
    __shared__ __align__(16) uint16_t gsm[3 * (ASLAB + BSLAB)];
    uint16_t* As = gsm;                    // [3][64][40]
    uint16_t* Ws = gsm + 3 * ASLAB;        // [3][128][40]

    const int t    = threadIdx.x;
    const int warp = t >> 5;
    const int lane = t & 31;
    const int grp  = lane >> 2;
    const int tig  = lane & 3;
    const int wm   = (warp >> 1) * 32;     // 2 warps in m (32 rows each)
    const int wn   = (warp & 1) * 64;      // 2 warps in n (64 cols each)
    const int brow = blockIdx.y * 64;
    const int bcol = blockIdx.x * 128;

    // staging: thread t -> row (t>>1) of A, B-low, B-high; col chunk (t&1)*16
    const int sr = t >> 1;
    const int sc = (t & 1) * 16;
    const uint16_t* gA  = (const uint16_t*)Abf + (size_t)(brow + sr) * K + sc;
    const uint16_t* gB0 = (const uint16_t*)Wbf + (size_t)(bcol + sr) * K + sc;
    const uint16_t* gB1 = (const uint16_t*)Wbf + (size_t)(bcol + 64 + sr) * K + sc;
    const uint32_t sA  = (uint32_t)__cvta_generic_to_shared(As + sr * 40 + sc);
    const uint32_t sB0 = (uint32_t)__cvta_generic_to_shared(Ws + sr * 40 + sc);
    const uint32_t sB1 = (uint32_t)__cvta_generic_to_shared(Ws + (64 + sr) * 40 + sc);

    const uint32_t stA0 = (uint32_t)__cvta_generic_to_shared(As);
    const uint32_t stB0 = (uint32_t)__cvta_generic_to_shared(Ws);
    uint32_t aoff[2], boff[4];
#pragma unroll
    for (int mt = 0; mt < 2; mt++)
        aoff[mt] = ((wm + mt * 16 + (lane & 15)) * 40 + ((lane >> 4) & 1) * 8) * 2;
#pragma unroll
    for (int p = 0; p < 4; p++)
        boff[p] = ((wn + 16 * p + (lane & 7) + ((lane >> 4) & 1) * 8) * 40
                   + ((lane >> 3) & 1) * 8) * 2;

    const int NS = K >> 5;

#define GPREF(s) do { \
        const uint32_t _oa = ((s) % 3) * (ASLAB * 2); \
        const uint32_t _ob = ((s) % 3) * (BSLAB * 2); \
        cpa16(sA  + _oa, gA  + (s) * 32); cpa16(sA  + _oa + 16, gA  + (s) * 32 + 8); \
        cpa16(sB0 + _ob, gB0 + (s) * 32); cpa16(sB0 + _ob + 16, gB0 + (s) * 32 + 8); \
        cpa16(sB1 + _ob, gB1 + (s) * 32); cpa16(sB1 + _ob + 16, gB1 + (s) * 32 + 8); \
        cpa_commit(); \
    } while (0)

    GPREF(0);
    GPREF(1);

    float acc[2][8][4];
#pragma unroll
    for (int mt = 0; mt < 2; mt++)
#pragma unroll
        for (int nt = 0; nt < 8; nt++)
#pragma unroll
            for (int r = 0; r < 4; r++) acc[mt][nt][r] = 0.f;

    for (int s = 0; s < NS; s++) {
        if (s == NS - 1) cpa_wait0(); else cpa_wait1();
        __syncthreads();
        if (s + 2 < NS) GPREF(s + 2);

        const uint32_t stgA = stA0 + (s % 3) * (ASLAB * 2);
        const uint32_t stgB = stB0 + (s % 3) * (BSLAB * 2);
#pragma unroll
        for (int ks = 0; ks < 2; ks++) {
            const uint32_t kb = ks * 32;
            uint32_t afr[2][4];
#pragma unroll
            for (int mt = 0; mt < 2; mt++) ldsm_x4(afr[mt], stgA + kb + aoff[mt]);
            uint32_t bfr[4][4];
#pragma unroll
            for (int p = 0; p < 4; p++)  ldsm_x4(bfr[p], stgB + kb + boff[p]);
#pragma unroll
            for (int mt = 0; mt < 2; mt++)
#pragma unroll
                for (int p = 0; p < 4; p++) {
                    mma_bf16(acc[mt][2*p  ], afr[mt], &bfr[p][0]);
                    mma_bf16(acc[mt][2*p+1], afr[mt], &bfr[p][2]);
                }
        }
    }

    // epilogue
#pragma unroll
    for (int mt = 0; mt < 2; mt++) {
#pragma unroll
        for (int half = 0; half < 2; half++) {
            const int grow = brow + wm + 16 * mt + grp + 8 * half;
            const float* rrow = (MODE == 1) ? (resid + (size_t)grow * N + bcol) : nullptr;
#pragma unroll
            for (int nt = 0; nt < 8; nt++) {
                const int col = wn + 8 * nt + 2 * tig;
                float ox = acc[mt][nt][2 * half + 0] + bias[bcol + col];
                float oy = acc[mt][nt][2 * half + 1] + bias[bcol + col + 1];
                if (MODE == 1) {
                    const float2 rv = *(const float2*)(rrow + col);
                    ox += rv.x; oy += rv.y;
                    float2 o; o.x = ox; o.y = oy;
                    *(float2*)((float*)Cout + (size_t)grow * N + bcol + col) = o;
                } else {
                    if (MODE == 2) { ox = fmaxf(ox, 0.f); oy = fmaxf(oy, 0.f); }
                    ((uint32_t*)Cout)[((size_t)grow * N + bcol + col) >> 1] = bfpack(ox, oy);
                }
            }
        }
    }
}

// ============ sliding-window flash attention, full bf16 mma ==================
// Q tile 64 rows, 4 warps (16 rows each). P stays in registers (C->A repack).
// K B-frags: plain ldmatrix; V B-frags: ldmatrix.trans. Stride 72 conflict-free.
#define QK_STR 72
#define KVBUF  (64 * QK_STR)     // uint16 elems per buffer

__global__ __launch_bounds__(128)
void attn_bf(const uint16_t* __restrict__ qkv, uint32_t* __restrict__ ctxbf,
             const int* __restrict__ wptr)
{
    __shared__ __align__(16) uint16_t Qs[KVBUF];
    __shared__ __align__(16) uint16_t Ks[2][KVBUF];
    __shared__ __align__(16) uint16_t Vs[2][KVBUF];

    int w = *wptr;
    if (w < 0 || w > 1000000) w = (int)__int_as_float((unsigned)w);

    const int t    = threadIdx.x;
    const int warp = t >> 5;
    const int lane = t & 31;
    const int grp  = lane >> 2;
    const int tig  = lane & 3;
    const int wm   = warp * 16;
    const int q0   = blockIdx.x * 64;
    const int h    = blockIdx.y;
    const int b    = blockIdx.z;

    const uint32_t qsb = (uint32_t)__cvta_generic_to_shared(Qs);
    const uint32_t ksb = (uint32_t)__cvta_generic_to_shared(Ks);
    const uint32_t vsb = (uint32_t)__cvta_generic_to_shared(Vs);

    int j0s = q0 - w; if (j0s < 0) j0s = 0; j0s &= ~63;
    int jend = q0 + 64 + w; if (jend > SS) jend = SS;
    const int ntl = (jend - j0s + 63) >> 6;

    const int pr  = t & 63;
    const int isV = t >> 6;
#define APREF(ti, buf) do { \
        const int _jr = j0s + (ti) * 64 + pr; \
        const int _sz = (_jr < SS) ? 16 : 0; \
        const int _jc = (_jr < SS) ? _jr : (SS - 1); \
        const uint16_t* _src = qkv + ((size_t)(b * SS + _jc)) * 1536 + 512 + isV * 512 + h * 64; \
        const uint32_t _dst = (isV ? vsb : ksb) + (buf) * (KVBUF * 2) + pr * (QK_STR * 2); \
        _Pragma("unroll") \
        for (int _ci = 0; _ci < 8; _ci++) cpa16z(_dst + 16 * _ci, _src + 8 * _ci, _sz); \
        cpa_commit(); \
    } while (0)

    // stage Q (cp.async) + start tile-0 prefetch
    {
        const int qr = t >> 1, qh = (t & 1) * 32;
        const uint16_t* qp = qkv + ((size_t)(b * SS + q0 + qr)) * 1536 + h * 64 + qh;
        const uint32_t qd = qsb + (qr * QK_STR + qh) * 2;
#pragma unroll
        for (int i = 0; i < 4; i++) cpa16(qd + 16 * i, qp + 8 * i);
    }
    APREF(0, 0);
    cpa_wait0();
    __syncthreads();

    // Q A-fragments (registers, reused across all tiles)
    uint32_t aq[4][4];
#pragma unroll
    for (int kt = 0; kt < 4; kt++)
        ldsm_x4(aq[kt], qsb + ((wm + (lane & 15)) * QK_STR + kt * 16 + ((lane >> 4) & 1) * 8) * 2);

    uint32_t koff[4], voff[4];
#pragma unroll
    for (int p = 0; p < 4; p++) {
        koff[p] = ((16 * p + (lane & 7) + ((lane >> 4) & 1) * 8) * QK_STR
                   + ((lane >> 3) & 1) * 8) * 2;
        voff[p] = (((lane & 7) + ((lane >> 3) & 1) * 8) * QK_STR
                   + p * 16 + ((lane >> 4) & 1) * 8) * 2;
    }

    float oc[8][4];
#pragma unroll
    for (int nt = 0; nt < 8; nt++) { oc[nt][0]=0.f; oc[nt][1]=0.f; oc[nt][2]=0.f; oc[nt][3]=0.f; }
    float m0 = -1e30f, m1 = -1e30f, l0 = 0.f, l1 = 0.f;
    const int qg0 = q0 + wm + grp, qg1 = qg0 + 8;

    for (int ti = 0; ti < ntl; ti++) {
        if (ti + 1 < ntl) { APREF(ti + 1, (ti + 1) & 1); cpa_wait1(); }
        else              { cpa_wait0(); }
        __syncthreads();

        const uint32_t kbase = ksb + (ti & 1) * (KVBUF * 2);
        const uint32_t vbase = vsb + (ti & 1) * (KVBUF * 2);
        const int j0 = j0s + ti * 64;

        // ---- S = Q @ K^T (bf16) ------------------------------------------
        float sc[8][4];
#pragma unroll
        for (int nt = 0; nt < 8; nt++) { sc[nt][0]=0.f; sc[nt][1]=0.f; sc[nt][2]=0.f; sc[nt][3]=0.f; }
#pragma unroll
        for (int kd = 0; kd < 4; kd++) {
#pragma unroll
            for (int p = 0; p < 4; p++) {
                uint32_t bq[4];
                ldsm_x4(bq, kbase + koff[p] + kd * 32);
                mma_bf16(sc[2*p  ], aq[kd], &bq[0]);
                mma_bf16(sc[2*p+1], aq[kd], &bq[2]);
            }
        }

        // ---- scale + mask + online softmax -------------------------------
        float tm0 = -1e30f, tm1 = -1e30f;
#pragma unroll
        for (int nt = 0; nt < 8; nt++) {
            sc[nt][0] *= 0.125f; sc[nt][1] *= 0.125f;
            sc[nt][2] *= 0.125f; sc[nt][3] *= 0.125f;
            const int ja = j0 + 8 * nt + 2 * tig;
            const int jb = ja + 1;
            if (ja >= SS || abs(qg0 - ja) > w) sc[nt][0] = -1e30f;
            if (jb >= SS || abs(qg0 - jb) > w) sc[nt][1] = -1e30f;
            if (ja >= SS || abs(qg1 - ja) > w) sc[nt][2] = -1e30f;
            if (jb >= SS || abs(qg1 - jb) > w) sc[nt][3] = -1e30f;
            tm0 = fmaxf(tm0, fmaxf(sc[nt][0], sc[nt][1]));
            tm1 = fmaxf(tm1, fmaxf(sc[nt][2], sc[nt][3]));
        }
        tm0 = fmaxf(tm0, __shfl_xor_sync(0xffffffffu, tm0, 1));
        tm0 = fmaxf(tm0, __shfl_xor_sync(0xffffffffu, tm0, 2));
        tm1 = fmaxf(tm1, __shfl_xor_sync(0xffffffffu, tm1, 1));
        tm1 = fmaxf(tm1, __shfl_xor_sync(0xffffffffu, tm1, 2));
        const float mn0 = fmaxf(m0, tm0), mn1 = fmaxf(m1, tm1);
        const float cf0 = __expf(m0 - mn0), cf1 = __expf(m1 - mn1);
        l0 *= cf0; l1 *= cf1;
#pragma unroll
        for (int nt = 0; nt < 8; nt++) {
            oc[nt][0] *= cf0; oc[nt][1] *= cf0;
            oc[nt][2] *= cf1; oc[nt][3] *= cf1;
        }
        float rs0 = 0.f, rs1 = 0.f;
#pragma unroll
        for (int nt = 0; nt < 8; nt++) {
            sc[nt][0] = __expf(sc[nt][0] - mn0);
            sc[nt][1] = __expf(sc[nt][1] - mn0);
            sc[nt][2] = __expf(sc[nt][2] - mn1);
            sc[nt][3] = __expf(sc[nt][3] - mn1);
            rs0 += sc[nt][0] + sc[nt][1];
            rs1 += sc[nt][2] + sc[nt][3];
        }
        rs0 += __shfl_xor_sync(0xffffffffu, rs0, 1);
        rs0 += __shfl_xor_sync(0xffffffffu, rs0, 2);
        rs1 += __shfl_xor_sync(0xffffffffu, rs1, 1);
        rs1 += __shfl_xor_sync(0xffffffffu, rs1, 2);
        l0 += rs0; l1 += rs1;
        m0 = mn0; m1 = mn1;

        // ---- P C-frags -> A-frags entirely in registers ------------------
        uint32_t ap[4][4];
#pragma unroll
        for (int jt = 0; jt < 4; jt++) {
            ap[jt][0] = bfpack(sc[2*jt  ][0], sc[2*jt  ][1]);
            ap[jt][1] = bfpack(sc[2*jt  ][2], sc[2*jt  ][3]);
            ap[jt][2] = bfpack(sc[2*jt+1][0], sc[2*jt+1][1]);
            ap[jt][3] = bfpack(sc[2*jt+1][2], sc[2*jt+1][3]);
        }

        // ---- O += P @ V (V^T via ldmatrix.trans) -------------------------
#pragma unroll
        for (int jt = 0; jt < 4; jt++) {
            const uint32_t jb2 = vbase + jt * (16 * QK_STR * 2);
#pragma unroll
            for (int p = 0; p < 4; p++) {
                uint32_t bv[4];
                ldsm_x4t(bv, jb2 + voff[p]);
                mma_bf16(oc[2*p  ], ap[jt], &bv[0]);
                mma_bf16(oc[2*p+1], ap[jt], &bv[2]);
            }
        }
        __syncthreads();   // done with this K/V buffer before refill
    }

    const float inv0 = 1.f / l0, inv1 = 1.f / l1;
    uint32_t* c0p = ctxbf + (((size_t)(b * SS + qg0)) * DD + h * 64) / 2;
    uint32_t* c1p = ctxbf + (((size_t)(b * SS + qg1)) * DD + h * 64) / 2;
#pragma unroll
    for (int nt = 0; nt < 8; nt++) {
        const int d = 8 * nt + 2 * tig;
        c0p[d >> 1] = bfpack(oc[nt][0] * inv0, oc[nt][1] * inv0);
        c1p[d >> 1] = bfpack(oc[nt][2] * inv1, oc[nt][3] * inv1);
    }
}

// ---------------- LayerNorm (one block per row, D=512) ----------------------
__global__ __launch_bounds__(128)
void ln_kernel(const float* __restrict__ in, const float* __restrict__ g,
               const float* __restrict__ b, float* __restrict__ out,
               uint32_t* __restrict__ outbf)
{
    __shared__ float red[4];
    const int row = blockIdx.x;
    const int t = threadIdx.x;
    float4 v = ((const float4*)(in + (size_t)row * DD))[t];

    float s = v.x + v.y + v.z + v.w;
#pragma unroll
    for (int o1 = 16; o1; o1 >>= 1) s += __shfl_xor_sync(0xffffffffu, s, o1);
    if ((t & 31) == 0) red[t >> 5] = s;
    __syncthreads();
    const float mean = (red[0] + red[1] + red[2] + red[3]) * (1.f / 512.f);

    const float dx0 = v.x - mean, dx1 = v.y - mean, dx2 = v.z - mean, dx3 = v.w - mean;
    float sq = dx0*dx0 + dx1*dx1 + dx2*dx2 + dx3*dx3;
#pragma unroll
    for (int o1 = 16; o1; o1 >>= 1) sq += __shfl_xor_sync(0xffffffffu, sq, o1);
    __syncthreads();
    if ((t & 31) == 0) red[t >> 5] = sq;
    __syncthreads();
    const float var = (red[0] + red[1] + red[2] + red[3]) * (1.f / 512.f);
    const float rs = rsqrtf(var + 1e-5f);

    float4 gv = ((const float4*)g)[t];
    float4 bv = ((const float4*)b)[t];
    float4 ov;
    ov.x = dx0 * rs * gv.x + bv.x;
    ov.y = dx1 * rs * gv.y + bv.y;
    ov.z = dx2 * rs * gv.z + bv.z;
    ov.w = dx3 * rs * gv.w + bv.w;
    ((float4*)(out + (size_t)row * DD))[t] = ov;
    if (outbf) {
        uint2 p;
        p.x = bfpack(ov.x, ov.y);
        p.y = bfpack(ov.z, ov.w);
        ((uint2*)(outbf + (size_t)row * DD / 2))[t] = p;
    }
}

// ---------------- launch ----------------------------------------------------
extern "C" void kernel_launch(void* const* d_in, const int* in_sizes, int n_in,
                              void* d_out, int out_size)
{
    const float* x     = (const float*)d_in[0];
    const float* w_in  = (const float*)d_in[1];
    const float* b_in  = (const float*)d_in[2];
    const float* w_out = (const float*)d_in[3];
    const float* b_out = (const float*)d_in[4];
    const float* ln1g  = (const float*)d_in[5];
    const float* ln1b  = (const float*)d_in[6];
    const float* ln2g  = (const float*)d_in[7];
    const float* ln2b  = (const float*)d_in[8];
    const float* w1    = (const float*)d_in[9];
    const float* b1    = (const float*)d_in[10];
    const float* w2    = (const float*)d_in[11];
    const float* b2    = (const float*)d_in[12];
    const int*   wnd   = (const int*)d_in[13];

    float *r1, *hbuf;
    uint16_t* qkvbf;
    uint32_t *xbf, *ctxbf, *hbf, *midbf, *winbf, *woutbf, *w1bf, *w2bf;
    cudaGetSymbolAddress((void**)&qkvbf,  g_qkvbf);
    cudaGetSymbolAddress((void**)&r1,     g_r1);
    cudaGetSymbolAddress((void**)&hbuf,   g_h);
    cudaGetSymbolAddress((void**)&xbf,    g_xbf);
    cudaGetSymbolAddress((void**)&ctxbf,  g_ctxbf);
    cudaGetSymbolAddress((void**)&hbf,    g_hbf);
    cudaGetSymbolAddress((void**)&midbf,  g_midbf);
    cudaGetSymbolAddress((void**)&winbf,  g_winbf);
    cudaGetSymbolAddress((void**)&woutbf, g_woutbf);
    cudaGetSymbolAddress((void**)&w1bf,   g_w1bf);
    cudaGetSymbolAddress((void**)&w2bf,   g_w2bf);

    // 0) fused bf16 conversions (x + all weights)
    cvtbf_all<<<CVT_TOT / 256, 256>>>(x, w_in, w_out, w1, w2,
                                      xbf, winbf, woutbf, w1bf, w2bf);
    // 1) fused QKV projection -> bf16 qkv   (12 x 128 = 1536 CTAs)
    gemm_bf<3><<<dim3(12, 128), 128>>>(xbf, winbf, b_in, nullptr, qkvbf, MM, 1536, DD);
    // 2) sliding-window flash attention (bf16) -> bf16 ctx
    attn_bf<<<dim3(SS / 64, HH, BB), 128>>>(qkvbf, ctxbf, wnd);
    // 3) out_proj + residual(x) -> fp32 r1  (4 x 128 = 512 CTAs)
    gemm_bf<1><<<dim3(4, 128), 128>>>(ctxbf, woutbf, b_out, x, r1, MM, DD, DD);
    // 4) LN1 -> fp32 h + bf16 shadow
    ln_kernel<<<MM, 128>>>(r1, ln1g, ln1b, hbuf, hbf);
    // 5) MLP fc1 + relu -> bf16 mid
    gemm_bf<2><<<dim3(4, 128), 128>>>(hbf, w1bf, b1, nullptr, midbf, MM, DD, DD);
    // 6) MLP fc2 + residual(h) -> fp32 r1
    gemm_bf<1><<<dim3(4, 128), 128>>>(midbf, w2bf, b2, hbuf, r1, MM, DD, DD);
    // 7) LN2 -> output
    ln_kernel<<<MM, 128>>>(r1, ln2g, ln2b, (float*)d_out, nullptr);
}

// round 14
// speedup vs baseline: 1.2390x; 1.0169x over previous
#include <cuda_runtime.h>
#include <cstdint>
#include <math.h>

// Problem constants (fixed shapes per reference)
#define BB   2
#define SS   4096
#define DD   512
#define HH   8
#define DHH  64
#define MM   (BB*SS)      // 8192 rows

// ---------------- scratch (device globals; no allocations allowed) ----------
__device__ uint16_t g_qkvbf[MM * 1536];         // bf16 qkv (attention input)
__device__ float    g_r1 [MM * DD];             // pre-LN buffer (reused)
__device__ float    g_h  [MM * DD];             // LN1 out fp32 (MLP residual)
__device__ uint32_t g_xbf   [MM * DD / 2];      // bf16x2 shadows
__device__ uint32_t g_ctxbf [MM * DD / 2];
__device__ uint32_t g_hbf   [MM * DD / 2];
__device__ uint32_t g_midbf [MM * DD / 2];
__device__ uint32_t g_winbf [1536 * DD / 2];
__device__ uint32_t g_woutbf[DD * DD / 2];
__device__ uint32_t g_w1bf  [DD * DD / 2];
__device__ uint32_t g_w2bf  [DD * DD / 2];

// ---------------- helpers ----------------------------------------------------
__device__ __forceinline__ uint32_t bfpack(float lo, float hi) {
    uint32_t r; asm("cvt.rn.bf16x2.f32 %0, %1, %2;" : "=r"(r) : "f"(hi), "f"(lo)); return r;
}
__device__ __forceinline__ void mma_bf16(float* d, const uint32_t* a, const uint32_t* b) {
    asm volatile(
        "mma.sync.aligned.m16n8k16.row.col.f32.bf16.bf16.f32 "
        "{%0,%1,%2,%3}, {%4,%5,%6,%7}, {%8,%9}, {%0,%1,%2,%3};"
        : "+f"(d[0]), "+f"(d[1]), "+f"(d[2]), "+f"(d[3])
        : "r"(a[0]), "r"(a[1]), "r"(a[2]), "r"(a[3]),
          "r"(b[0]), "r"(b[1]));
}
__device__ __forceinline__ void ldsm_x4(uint32_t* r, uint32_t addr) {
    asm volatile("ldmatrix.sync.aligned.m8n8.x4.shared.b16 {%0,%1,%2,%3}, [%4];"
        : "=r"(r[0]), "=r"(r[1]), "=r"(r[2]), "=r"(r[3]) : "r"(addr));
}
__device__ __forceinline__ void ldsm_x4t(uint32_t* r, uint32_t addr) {
    asm volatile("ldmatrix.sync.aligned.m8n8.x4.trans.shared.b16 {%0,%1,%2,%3}, [%4];"
        : "=r"(r[0]), "=r"(r[1]), "=r"(r[2]), "=r"(r[3]) : "r"(addr));
}
// GEMM staging: .cg (keep L1 free for ldmatrix). Attention: .ca.
__device__ __forceinline__ void cpa16cg(uint32_t d, const void* s) {
    asm volatile("cp.async.cg.shared.global [%0], [%1], 16;" :: "r"(d), "l"(s));
}
__device__ __forceinline__ void cpa16(uint32_t d, const void* s) {
    asm volatile("cp.async.ca.shared.global [%0], [%1], 16;" :: "r"(d), "l"(s));
}
__device__ __forceinline__ void cpa16z(uint32_t d, const void* s, int sz) {
    asm volatile("cp.async.ca.shared.global [%0], [%1], 16, %2;" :: "r"(d), "l"(s), "r"(sz));
}
__device__ __forceinline__ void cpa_commit() { asm volatile("cp.async.commit_group;" ::: "memory"); }
__device__ __forceinline__ void cpa_wait1()  { asm volatile("cp.async.wait_group 1;" ::: "memory"); }
__device__ __forceinline__ void cpa_wait0()  { asm volatile("cp.async.wait_group 0;" ::: "memory"); }

// ---------------- fused fp32 -> bf16x2 conversion (all 5 tensors) -----------
#define CVT_N0 1048576
#define CVT_N1 (CVT_N0 + 196608)
#define CVT_N2 (CVT_N1 + 65536)
#define CVT_N3 (CVT_N2 + 65536)
#define CVT_TOT (CVT_N3 + 65536)

__global__ __launch_bounds__(256)
void cvtbf_all(const float* __restrict__ x,    const float* __restrict__ win,
               const float* __restrict__ wout, const float* __restrict__ w1,
               const float* __restrict__ w2,
               uint32_t* __restrict__ xbf,    uint32_t* __restrict__ winbf,
               uint32_t* __restrict__ woutbf, uint32_t* __restrict__ w1bf,
               uint32_t* __restrict__ w2bf)
{
    const int i = blockIdx.x * 256 + threadIdx.x;
    const float* src; uint32_t* dst; int j;
    if (i < CVT_N0)      { src = x;    dst = xbf;    j = i; }
    else if (i < CVT_N1) { src = win;  dst = winbf;  j = i - CVT_N0; }
    else if (i < CVT_N2) { src = wout; dst = woutbf; j = i - CVT_N1; }
    else if (i < CVT_N3) { src = w1;   dst = w1bf;   j = i - CVT_N2; }
    else                 { src = w2;   dst = w2bf;   j = i - CVT_N3; }
    float4 v = ((const float4*)src)[j];
    uint2 p;
    p.x = bfpack(v.x, v.y);
    p.y = bfpack(v.z, v.w);
    ((uint2*)dst)[j] = p;
}

// ======== bf16 mma GEMM: CTA tile 64x64, 4 warps (32x32 warp tiles) ==========
// C = A @ W^T + bias (+epilogue). A:[M,K] bf16, W:[N,K] bf16. K mult of 32.
// Grid 1024 (512-GEMM) / 3072 (QKV); launch_bounds(128,5) -> ~20 warps/SM.
// MODE 1: fp32 +bias+resid; MODE 2: bf16 +bias+relu; MODE 3: bf16 +bias
#define ASLAB (64*40)              // elems per stage (A and B identical)

template<int MODE>
__global__ __launch_bounds__(128, 5)
void gemm_bf(const uint32_t* __restrict__ Abf, const uint32_t* __restrict__ Wbf,
             const float* __restrict__ bias, const float* __restrict__ resid,
             void* __restrict__ Cout, int M, int N, int K)
{
    __shared__ __align__(16) uint16_t gsm[6 * ASLAB];   // 30720 bytes
    uint16_t* As = gsm;                    // [3][64][40]
    uint16_t* Ws = gsm + 3 * ASLAB;        // [3][64][40]

    const int t    = threadIdx.x;
    const int warp = t >> 5;
    const int lane = t & 31;
    const int grp  = lane >> 2;
    const int tig  = lane & 3;
    const int wm   = (warp >> 1) * 32;     // 2 warps in m
    const int wn   = (warp & 1) * 32;      // 2 warps in n
    const int brow = blockIdx.y * 64;
    const int bcol = blockIdx.x * 64;

    // staging: thread t -> row (t>>1), col chunk (t&1)*16, for both A and B
    const int sr = t >> 1;
    const int sc = (t & 1) * 16;
    const uint16_t* gA = (const uint16_t*)Abf + (size_t)(brow + sr) * K + sc;
    const uint16_t* gB = (const uint16_t*)Wbf + (size_t)(bcol + sr) * K + sc;
    const uint32_t sA = (uint32_t)__cvta_generic_to_shared(As + sr * 40 + sc);
    const uint32_t sB = (uint32_t)__cvta_generic_to_shared(Ws + sr * 40 + sc);

    const uint32_t stA0 = (uint32_t)__cvta_generic_to_shared(As);
    const uint32_t stB0 = (uint32_t)__cvta_generic_to_shared(Ws);
    uint32_t aoff[2], boff[2];
#pragma unroll
    for (int mt = 0; mt < 2; mt++)
        aoff[mt] = ((wm + mt * 16 + (lane & 15)) * 40 + ((lane >> 4) & 1) * 8) * 2;
#pragma unroll
    for (int p = 0; p < 2; p++)
        boff[p] = ((wn + 16 * p + (lane & 7) + ((lane >> 4) & 1) * 8) * 40
                   + ((lane >> 3) & 1) * 8) * 2;

    const int NS = K >> 5;

#define GPREF(s) do { \
        const uint32_t _o = ((s) % 3) * (ASLAB * 2); \
        cpa16cg(sA + _o, gA + (s) * 32); cpa16cg(sA + _o + 16, gA + (s) * 32 + 8); \
        cpa16cg(sB + _o, gB + (s) * 32); cpa16cg(sB + _o + 16, gB + (s) * 32 + 8); \
        cpa_commit(); \
    } while (0)

    GPREF(0);
    GPREF(1);

    float acc[2][4][4];
#pragma unroll
    for (int mt = 0; mt < 2; mt++)
#pragma unroll
        for (int nt = 0; nt < 4; nt++)
#pragma unroll
            for (int r = 0; r < 4; r++) acc[mt][nt][r] = 0.f;

    for (int s = 0; s < NS; s++) {
        if (s == NS - 1) cpa_wait0(); else cpa_wait1();
        __syncthreads();
        if (s + 2 < NS) GPREF(s + 2);

        const uint32_t stgA = stA0 + (s % 3) * (ASLAB * 2);
        const uint32_t stgB = stB0 + (s % 3) * (ASLAB * 2);
#pragma unroll
        for (int ks = 0; ks < 2; ks++) {
            const uint32_t kb = ks * 32;
            uint32_t afr[2][4];
#pragma unroll
            for (int mt = 0; mt < 2; mt++) ldsm_x4(afr[mt], stgA + kb + aoff[mt]);
            uint32_t bfr[2][4];
#pragma unroll
            for (int p = 0; p < 2; p++)  ldsm_x4(bfr[p], stgB + kb + boff[p]);
#pragma unroll
            for (int mt = 0; mt < 2; mt++)
#pragma unroll
                for (int p = 0; p < 2; p++) {
                    mma_bf16(acc[mt][2*p  ], afr[mt], &bfr[p][0]);
                    mma_bf16(acc[mt][2*p+1], afr[mt], &bfr[p][2]);
                }
        }
    }

    // epilogue
#pragma unroll
    for (int mt = 0; mt < 2; mt++) {
#pragma unroll
        for (int half = 0; half < 2; half++) {
            const int grow = brow + wm + 16 * mt + grp + 8 * half;
            const float* rrow = (MODE == 1) ? (resid + (size_t)grow * N + bcol) : nullptr;
#pragma unroll
            for (int nt = 0; nt < 4; nt++) {
                const int col = wn + 8 * nt + 2 * tig;
                float ox = acc[mt][nt][2 * half + 0] + bias[bcol + col];
                float oy = acc[mt][nt][2 * half + 1] + bias[bcol + col + 1];
                if (MODE == 1) {
                    const float2 rv = *(const float2*)(rrow + col);
                    ox += rv.x; oy += rv.y;
                    float2 o; o.x = ox; o.y = oy;
                    *(float2*)((float*)Cout + (size_t)grow * N + bcol + col) = o;
                } else {
                    if (MODE == 2) { ox = fmaxf(ox, 0.f); oy = fmaxf(oy, 0.f); }
                    ((uint32_t*)Cout)[((size_t)grow * N + bcol + col) >> 1] = bfpack(ox, oy);
                }
            }
        }
    }
}

// ============ sliding-window flash attention, full bf16 mma ==================
// Q tile 64 rows, 4 warps (16 rows each). P stays in registers (C->A repack).
// K B-frags: plain ldmatrix; V B-frags: ldmatrix.trans. Stride 72 conflict-free.
#define QK_STR 72
#define KVBUF  (64 * QK_STR)     // uint16 elems per buffer

__global__ __launch_bounds__(128)
void attn_bf(const uint16_t* __restrict__ qkv, uint32_t* __restrict__ ctxbf,
             const int* __restrict__ wptr)
{
    __shared__ __align__(16) uint16_t Qs[KVBUF];
    __shared__ __align__(16) uint16_t Ks[2][KVBUF];
    __shared__ __align__(16) uint16_t Vs[2][KVBUF];

    int w = *wptr;
    if (w < 0 || w > 1000000) w = (int)__int_as_float((unsigned)w);

    const int t    = threadIdx.x;
    const int warp = t >> 5;
    const int lane = t & 31;
    const int grp  = lane >> 2;
    const int tig  = lane & 3;
    const int wm   = warp * 16;
    const int q0   = blockIdx.x * 64;
    const int h    = blockIdx.y;
    const int b    = blockIdx.z;

    const uint32_t qsb = (uint32_t)__cvta_generic_to_shared(Qs);
    const uint32_t ksb = (uint32_t)__cvta_generic_to_shared(Ks);
    const uint32_t vsb = (uint32_t)__cvta_generic_to_shared(Vs);

    int j0s = q0 - w; if (j0s < 0) j0s = 0; j0s &= ~63;
    int jend = q0 + 64 + w; if (jend > SS) jend = SS;
    const int ntl = (jend - j0s + 63) >> 6;

    const int pr  = t & 63;
    const int isV = t >> 6;
#define APREF(ti, buf) do { \
        const int _jr = j0s + (ti) * 64 + pr; \
        const int _sz = (_jr < SS) ? 16 : 0; \
        const int _jc = (_jr < SS) ? _jr : (SS - 1); \
        const uint16_t* _src = qkv + ((size_t)(b * SS + _jc)) * 1536 + 512 + isV * 512 + h * 64; \
        const uint32_t _dst = (isV ? vsb : ksb) + (buf) * (KVBUF * 2) + pr * (QK_STR * 2); \
        _Pragma("unroll") \
        for (int _ci = 0; _ci < 8; _ci++) cpa16z(_dst + 16 * _ci, _src + 8 * _ci, _sz); \
        cpa_commit(); \
    } while (0)

    // stage Q (cp.async) + start tile-0 prefetch
    {
        const int qr = t >> 1, qh = (t & 1) * 32;
        const uint16_t* qp = qkv + ((size_t)(b * SS + q0 + qr)) * 1536 + h * 64 + qh;
        const uint32_t qd = qsb + (qr * QK_STR + qh) * 2;
#pragma unroll
        for (int i = 0; i < 4; i++) cpa16(qd + 16 * i, qp + 8 * i);
    }
    APREF(0, 0);
    cpa_wait0();
    __syncthreads();

    // Q A-fragments (registers, reused across all tiles)
    uint32_t aq[4][4];
#pragma unroll
    for (int kt = 0; kt < 4; kt++)
        ldsm_x4(aq[kt], qsb + ((wm + (lane & 15)) * QK_STR + kt * 16 + ((lane >> 4) & 1) * 8) * 2);

    uint32_t koff[4], voff[4];
#pragma unroll
    for (int p = 0; p < 4; p++) {
        koff[p] = ((16 * p + (lane & 7) + ((lane >> 4) & 1) * 8) * QK_STR
                   + ((lane >> 3) & 1) * 8) * 2;
        voff[p] = (((lane & 7) + ((lane >> 3) & 1) * 8) * QK_STR
                   + p * 16 + ((lane >> 4) & 1) * 8) * 2;
    }

    float oc[8][4];
#pragma unroll
    for (int nt = 0; nt < 8; nt++) { oc[nt][0]=0.f; oc[nt][1]=0.f; oc[nt][2]=0.f; oc[nt][3]=0.f; }
    float m0 = -1e30f, m1 = -1e30f, l0 = 0.f, l1 = 0.f;
    const int qg0 = q0 + wm + grp, qg1 = qg0 + 8;

    for (int ti = 0; ti < ntl; ti++) {
        if (ti + 1 < ntl) { APREF(ti + 1, (ti + 1) & 1); cpa_wait1(); }
        else              { cpa_wait0(); }
        __syncthreads();

        const uint32_t kbase = ksb + (ti & 1) * (KVBUF * 2);
        const uint32_t vbase = vsb + (ti & 1) * (KVBUF * 2);
        const int j0 = j0s + ti * 64;

        // ---- S = Q @ K^T (bf16) ------------------------------------------
        float sc[8][4];
#pragma unroll
        for (int nt = 0; nt < 8; nt++) { sc[nt][0]=0.f; sc[nt][1]=0.f; sc[nt][2]=0.f; sc[nt][3]=0.f; }
#pragma unroll
        for (int kd = 0; kd < 4; kd++) {
#pragma unroll
            for (int p = 0; p < 4; p++) {
                uint32_t bq[4];
                ldsm_x4(bq, kbase + koff[p] + kd * 32);
                mma_bf16(sc[2*p  ], aq[kd], &bq[0]);
                mma_bf16(sc[2*p+1], aq[kd], &bq[2]);
            }
        }

        // ---- scale + mask + online softmax -------------------------------
        float tm0 = -1e30f, tm1 = -1e30f;
#pragma unroll
        for (int nt = 0; nt < 8; nt++) {
            sc[nt][0] *= 0.125f; sc[nt][1] *= 0.125f;
            sc[nt][2] *= 0.125f; sc[nt][3] *= 0.125f;
            const int ja = j0 + 8 * nt + 2 * tig;
            const int jb = ja + 1;
            if (ja >= SS || abs(qg0 - ja) > w) sc[nt][0] = -1e30f;
            if (jb >= SS || abs(qg0 - jb) > w) sc[nt][1] = -1e30f;
            if (ja >= SS || abs(qg1 - ja) > w) sc[nt][2] = -1e30f;
            if (jb >= SS || abs(qg1 - jb) > w) sc[nt][3] = -1e30f;
            tm0 = fmaxf(tm0, fmaxf(sc[nt][0], sc[nt][1]));
            tm1 = fmaxf(tm1, fmaxf(sc[nt][2], sc[nt][3]));
        }
        tm0 = fmaxf(tm0, __shfl_xor_sync(0xffffffffu, tm0, 1));
        tm0 = fmaxf(tm0, __shfl_xor_sync(0xffffffffu, tm0, 2));
        tm1 = fmaxf(tm1, __shfl_xor_sync(0xffffffffu, tm1, 1));
        tm1 = fmaxf(tm1, __shfl_xor_sync(0xffffffffu, tm1, 2));
        const float mn0 = fmaxf(m0, tm0), mn1 = fmaxf(m1, tm1);
        const float cf0 = __expf(m0 - mn0), cf1 = __expf(m1 - mn1);
        l0 *= cf0; l1 *= cf1;
#pragma unroll
        for (int nt = 0; nt < 8; nt++) {
            oc[nt][0] *= cf0; oc[nt][1] *= cf0;
            oc[nt][2] *= cf1; oc[nt][3] *= cf1;
        }
        float rs0 = 0.f, rs1 = 0.f;
#pragma unroll
        for (int nt = 0; nt < 8; nt++) {
            sc[nt][0] = __expf(sc[nt][0] - mn0);
            sc[nt][1] = __expf(sc[nt][1] - mn0);
            sc[nt][2] = __expf(sc[nt][2] - mn1);
            sc[nt][3] = __expf(sc[nt][3] - mn1);
            rs0 += sc[nt][0] + sc[nt][1];
            rs1 += sc[nt][2] + sc[nt][3];
        }
        rs0 += __shfl_xor_sync(0xffffffffu, rs0, 1);
        rs0 += __shfl_xor_sync(0xffffffffu, rs0, 2);
        rs1 += __shfl_xor_sync(0xffffffffu, rs1, 1);
        rs1 += __shfl_xor_sync(0xffffffffu, rs1, 2);
        l0 += rs0; l1 += rs1;
        m0 = mn0; m1 = mn1;

        // ---- P C-frags -> A-frags entirely in registers ------------------
        uint32_t ap[4][4];
#pragma unroll
        for (int jt = 0; jt < 4; jt++) {
            ap[jt][0] = bfpack(sc[2*jt  ][0], sc[2*jt  ][1]);
            ap[jt][1] = bfpack(sc[2*jt  ][2], sc[2*jt  ][3]);
            ap[jt][2] = bfpack(sc[2*jt+1][0], sc[2*jt+1][1]);
            ap[jt][3] = bfpack(sc[2*jt+1][2], sc[2*jt+1][3]);
        }

        // ---- O += P @ V (V^T via ldmatrix.trans) -------------------------
#pragma unroll
        for (int jt = 0; jt < 4; jt++) {
            const uint32_t jb2 = vbase + jt * (16 * QK_STR * 2);
#pragma unroll
            for (int p = 0; p < 4; p++) {
                uint32_t bv[4];
                ldsm_x4t(bv, jb2 + voff[p]);
                mma_bf16(oc[2*p  ], ap[jt], &bv[0]);
                mma_bf16(oc[2*p+1], ap[jt], &bv[2]);
            }
        }
        __syncthreads();   // done with this K/V buffer before refill
    }

    const float inv0 = 1.f / l0, inv1 = 1.f / l1;
    uint32_t* c0p = ctxbf + (((size_t)(b * SS + qg0)) * DD + h * 64) / 2;
    uint32_t* c1p = ctxbf + (((size_t)(b * SS + qg1)) * DD + h * 64) / 2;
#pragma unroll
    for (int nt = 0; nt < 8; nt++) {
        const int d = 8 * nt + 2 * tig;
        c0p[d >> 1] = bfpack(oc[nt][0] * inv0, oc[nt][1] * inv0);
        c1p[d >> 1] = bfpack(oc[nt][2] * inv1, oc[nt][3] * inv1);
    }
}

// ---------------- LayerNorm (one block per row, D=512) ----------------------
__global__ __launch_bounds__(128)
void ln_kernel(const float* __restrict__ in, const float* __restrict__ g,
               const float* __restrict__ b, float* __restrict__ out,
               uint32_t* __restrict__ outbf)
{
    __shared__ float red[4];
    const int row = blockIdx.x;
    const int t = threadIdx.x;
    float4 v = ((const float4*)(in + (size_t)row * DD))[t];

    float s = v.x + v.y + v.z + v.w;
#pragma unroll
    for (int o1 = 16; o1; o1 >>= 1) s += __shfl_xor_sync(0xffffffffu, s, o1);
    if ((t & 31) == 0) red[t >> 5] = s;
    __syncthreads();
    const float mean = (red[0] + red[1] + red[2] + red[3]) * (1.f / 512.f);

    const float dx0 = v.x - mean, dx1 = v.y - mean, dx2 = v.z - mean, dx3 = v.w - mean;
    float sq = dx0*dx0 + dx1*dx1 + dx2*dx2 + dx3*dx3;
#pragma unroll
    for (int o1 = 16; o1; o1 >>= 1) sq += __shfl_xor_sync(0xffffffffu, sq, o1);
    __syncthreads();
    if ((t & 31) == 0) red[t >> 5] = sq;
    __syncthreads();
    const float var = (red[0] + red[1] + red[2] + red[3]) * (1.f / 512.f);
    const float rs = rsqrtf(var + 1e-5f);

    float4 gv = ((const float4*)g)[t];
    float4 bv = ((const float4*)b)[t];
    float4 ov;
    ov.x = dx0 * rs * gv.x + bv.x;
    ov.y = dx1 * rs * gv.y + bv.y;
    ov.z = dx2 * rs * gv.z + bv.z;
    ov.w = dx3 * rs * gv.w + bv.w;
    ((float4*)(out + (size_t)row * DD))[t] = ov;
    if (outbf) {
        uint2 p;
        p.x = bfpack(ov.x, ov.y);
        p.y = bfpack(ov.z, ov.w);
        ((uint2*)(outbf + (size_t)row * DD / 2))[t] = p;
    }
}

// ---------------- launch ----------------------------------------------------
extern "C" void kernel_launch(void* const* d_in, const int* in_sizes, int n_in,
                              void* d_out, int out_size)
{
    const float* x     = (const float*)d_in[0];
    const float* w_in  = (const float*)d_in[1];
    const float* b_in  = (const float*)d_in[2];
    const float* w_out = (const float*)d_in[3];
    const float* b_out = (const float*)d_in[4];
    const float* ln1g  = (const float*)d_in[5];
    const float* ln1b  = (const float*)d_in[6];
    const float* ln2g  = (const float*)d_in[7];
    const float* ln2b  = (const float*)d_in[8];
    const float* w1    = (const float*)d_in[9];
    const float* b1    = (const float*)d_in[10];
    const float* w2    = (const float*)d_in[11];
    const float* b2    = (const float*)d_in[12];
    const int*   wnd   = (const int*)d_in[13];

    float *r1, *hbuf;
    uint16_t* qkvbf;
    uint32_t *xbf, *ctxbf, *hbf, *midbf, *winbf, *woutbf, *w1bf, *w2bf;
    cudaGetSymbolAddress((void**)&qkvbf,  g_qkvbf);
    cudaGetSymbolAddress((void**)&r1,     g_r1);
    cudaGetSymbolAddress((void**)&hbuf,   g_h);
    cudaGetSymbolAddress((void**)&xbf,    g_xbf);
    cudaGetSymbolAddress((void**)&ctxbf,  g_ctxbf);
    cudaGetSymbolAddress((void**)&hbf,    g_hbf);
    cudaGetSymbolAddress((void**)&midbf,  g_midbf);
    cudaGetSymbolAddress((void**)&winbf,  g_winbf);
    cudaGetSymbolAddress((void**)&woutbf, g_woutbf);
    cudaGetSymbolAddress((void**)&w1bf,   g_w1bf);
    cudaGetSymbolAddress((void**)&w2bf,   g_w2bf);

    // 0) fused bf16 conversions (x + all weights)
    cvtbf_all<<<CVT_TOT / 256, 256>>>(x, w_in, w_out, w1, w2,
                                      xbf, winbf, woutbf, w1bf, w2bf);
    // 1) fused QKV projection -> bf16 qkv   (24 x 128 = 3072 CTAs)
    gemm_bf<3><<<dim3(24, 128), 128>>>(xbf, winbf, b_in, nullptr, qkvbf, MM, 1536, DD);
    // 2) sliding-window flash attention (bf16) -> bf16 ctx
    attn_bf<<<dim3(SS / 64, HH, BB), 128>>>(qkvbf, ctxbf, wnd);
    // 3) out_proj + residual(x) -> fp32 r1  (8 x 128 = 1024 CTAs)
    gemm_bf<1><<<dim3(8, 128), 128>>>(ctxbf, woutbf, b_out, x, r1, MM, DD, DD);
    // 4) LN1 -> fp32 h + bf16 shadow
    ln_kernel<<<MM, 128>>>(r1, ln1g, ln1b, hbuf, hbf);
    // 5) MLP fc1 + relu -> bf16 mid
    gemm_bf<2><<<dim3(8, 128), 128>>>(hbf, w1bf, b1, nullptr, midbf, MM, DD, DD);
    // 6) MLP fc2 + residual(h) -> fp32 r1
    gemm_bf<1><<<dim3(8, 128), 128>>>(midbf, w2bf, b2, hbuf, r1, MM, DD, DD);
    // 7) LN2 -> output
    ln_kernel<<<MM, 128>>>(r1, ln2g, ln2b, (float*)d_out, nullptr);
}

// round 15
// speedup vs baseline: 1.2414x; 1.0019x over previous
#include <cuda_runtime.h>
#include <cstdint>
#include <math.h>

// Problem constants (fixed shapes per reference)
#define BB   2
#define SS   4096
#define DD   512
#define HH   8
#define DHH  64
#define MM   (BB*SS)      // 8192 rows

// ---------------- scratch (device globals; no allocations allowed) ----------
__device__ uint16_t g_qkvbf[MM * 1536];         // bf16 qkv (attention input)
__device__ float    g_r1 [MM * DD];             // pre-LN buffer (reused)
__device__ float    g_h  [MM * DD];             // LN1 out fp32 (MLP residual)
__device__ uint32_t g_xbf   [MM * DD / 2];      // bf16x2 shadows
__device__ uint32_t g_ctxbf [MM * DD / 2];
__device__ uint32_t g_hbf   [MM * DD / 2];
__device__ uint32_t g_midbf [MM * DD / 2];
__device__ uint32_t g_winbf [1536 * DD / 2];
__device__ uint32_t g_woutbf[DD * DD / 2];
__device__ uint32_t g_w1bf  [DD * DD / 2];
__device__ uint32_t g_w2bf  [DD * DD / 2];

// ---------------- helpers ----------------------------------------------------
__device__ __forceinline__ uint32_t bfpack(float lo, float hi) {
    uint32_t r; asm("cvt.rn.bf16x2.f32 %0, %1, %2;" : "=r"(r) : "f"(hi), "f"(lo)); return r;
}
__device__ __forceinline__ void mma_bf16(float* d, const uint32_t* a, const uint32_t* b) {
    asm volatile(
        "mma.sync.aligned.m16n8k16.row.col.f32.bf16.bf16.f32 "
        "{%0,%1,%2,%3}, {%4,%5,%6,%7}, {%8,%9}, {%0,%1,%2,%3};"
        : "+f"(d[0]), "+f"(d[1]), "+f"(d[2]), "+f"(d[3])
        : "r"(a[0]), "r"(a[1]), "r"(a[2]), "r"(a[3]),
          "r"(b[0]), "r"(b[1]));
}
__device__ __forceinline__ void ldsm_x4(uint32_t* r, uint32_t addr) {
    asm volatile("ldmatrix.sync.aligned.m8n8.x4.shared.b16 {%0,%1,%2,%3}, [%4];"
        : "=r"(r[0]), "=r"(r[1]), "=r"(r[2]), "=r"(r[3]) : "r"(addr));
}
__device__ __forceinline__ void ldsm_x4t(uint32_t* r, uint32_t addr) {
    asm volatile("ldmatrix.sync.aligned.m8n8.x4.trans.shared.b16 {%0,%1,%2,%3}, [%4];"
        : "=r"(r[0]), "=r"(r[1]), "=r"(r[2]), "=r"(r[3]) : "r"(addr));
}
// GEMM staging: .cg (keep L1 free for ldmatrix). Attention: .ca.
__device__ __forceinline__ void cpa16cg(uint32_t d, const void* s) {
    asm volatile("cp.async.cg.shared.global [%0], [%1], 16;" :: "r"(d), "l"(s));
}
__device__ __forceinline__ void cpa16(uint32_t d, const void* s) {
    asm volatile("cp.async.ca.shared.global [%0], [%1], 16;" :: "r"(d), "l"(s));
}
__device__ __forceinline__ void cpa16z(uint32_t d, const void* s, int sz) {
    asm volatile("cp.async.ca.shared.global [%0], [%1], 16, %2;" :: "r"(d), "l"(s), "r"(sz));
}
__device__ __forceinline__ void cpa_commit() { asm volatile("cp.async.commit_group;" ::: "memory"); }
__device__ __forceinline__ void cpa_wait2()  { asm volatile("cp.async.wait_group 2;" ::: "memory"); }
__device__ __forceinline__ void cpa_wait1()  { asm volatile("cp.async.wait_group 1;" ::: "memory"); }
__device__ __forceinline__ void cpa_wait0()  { asm volatile("cp.async.wait_group 0;" ::: "memory"); }

// ---------------- fused fp32 -> bf16x2 conversion (all 5 tensors) -----------
#define CVT_N0 1048576
#define CVT_N1 (CVT_N0 + 196608)
#define CVT_N2 (CVT_N1 + 65536)
#define CVT_N3 (CVT_N2 + 65536)
#define CVT_TOT (CVT_N3 + 65536)

__global__ __launch_bounds__(256)
void cvtbf_all(const float* __restrict__ x,    const float* __restrict__ win,
               const float* __restrict__ wout, const float* __restrict__ w1,
               const float* __restrict__ w2,
               uint32_t* __restrict__ xbf,    uint32_t* __restrict__ winbf,
               uint32_t* __restrict__ woutbf, uint32_t* __restrict__ w1bf,
               uint32_t* __restrict__ w2bf)
{
    const int i = blockIdx.x * 256 + threadIdx.x;
    const float* src; uint32_t* dst; int j;
    if (i < CVT_N0)      { src = x;    dst = xbf;    j = i; }
    else if (i < CVT_N1) { src = win;  dst = winbf;  j = i - CVT_N0; }
    else if (i < CVT_N2) { src = wout; dst = woutbf; j = i - CVT_N1; }
    else if (i < CVT_N3) { src = w1;   dst = w1bf;   j = i - CVT_N2; }
    else                 { src = w2;   dst = w2bf;   j = i - CVT_N3; }
    float4 v = ((const float4*)src)[j];
    uint2 p;
    p.x = bfpack(v.x, v.y);
    p.y = bfpack(v.z, v.w);
    ((uint2*)dst)[j] = p;
}

// ======== bf16 mma GEMM: CTA tile 64x64, 4 warps, 4-stage cp.async ring ======
// C = A @ W^T + bias (+epilogue). A:[M,K] bf16, W:[N,K] bf16. K mult of 32.
// Prefetch distance 3 stages; full-stage fragment batch (8 ldsm, then 16 mma).
// MODE 1: fp32 +bias+resid; MODE 2: bf16 +bias+relu; MODE 3: bf16 +bias
#define ASLAB (64*40)              // elems per stage (A and B identical)
#define NSTG  4

template<int MODE>
__global__ __launch_bounds__(128, 5)
void gemm_bf(const uint32_t* __restrict__ Abf, const uint32_t* __restrict__ Wbf,
             const float* __restrict__ bias, const float* __restrict__ resid,
             void* __restrict__ Cout, int M, int N, int K)
{
    __shared__ __align__(16) uint16_t gsm[2 * NSTG * ASLAB];   // 40960 bytes
    uint16_t* As = gsm;                       // [4][64][40]
    uint16_t* Ws = gsm + NSTG * ASLAB;        // [4][64][40]

    const int t    = threadIdx.x;
    const int warp = t >> 5;
    const int lane = t & 31;
    const int grp  = lane >> 2;
    const int tig  = lane & 3;
    const int wm   = (warp >> 1) * 32;     // 2 warps in m
    const int wn   = (warp & 1) * 32;      // 2 warps in n
    const int brow = blockIdx.y * 64;
    const int bcol = blockIdx.x * 64;

    // staging: thread t -> row (t>>1), col chunk (t&1)*16, for both A and B
    const int sr = t >> 1;
    const int sc = (t & 1) * 16;
    const uint16_t* gA = (const uint16_t*)Abf + (size_t)(brow + sr) * K + sc;
    const uint16_t* gB = (const uint16_t*)Wbf + (size_t)(bcol + sr) * K + sc;
    const uint32_t sA = (uint32_t)__cvta_generic_to_shared(As + sr * 40 + sc);
    const uint32_t sB = (uint32_t)__cvta_generic_to_shared(Ws + sr * 40 + sc);

    const uint32_t stA0 = (uint32_t)__cvta_generic_to_shared(As);
    const uint32_t stB0 = (uint32_t)__cvta_generic_to_shared(Ws);
    uint32_t aoff[2], boff[2];
#pragma unroll
    for (int mt = 0; mt < 2; mt++)
        aoff[mt] = ((wm + mt * 16 + (lane & 15)) * 40 + ((lane >> 4) & 1) * 8) * 2;
#pragma unroll
    for (int p = 0; p < 2; p++)
        boff[p] = ((wn + 16 * p + (lane & 7) + ((lane >> 4) & 1) * 8) * 40
                   + ((lane >> 3) & 1) * 8) * 2;

    const int NS = K >> 5;

#define GPREF(s) do { \
        const uint32_t _o = ((s) % NSTG) * (ASLAB * 2); \
        cpa16cg(sA + _o, gA + (s) * 32); cpa16cg(sA + _o + 16, gA + (s) * 32 + 8); \
        cpa16cg(sB + _o, gB + (s) * 32); cpa16cg(sB + _o + 16, gB + (s) * 32 + 8); \
        cpa_commit(); \
    } while (0)

    GPREF(0);
    GPREF(1);
    GPREF(2);

    float acc[2][4][4];
#pragma unroll
    for (int mt = 0; mt < 2; mt++)
#pragma unroll
        for (int nt = 0; nt < 4; nt++)
#pragma unroll
            for (int r = 0; r < 4; r++) acc[mt][nt][r] = 0.f;

    for (int s = 0; s < NS; s++) {
        if (s + 1 >= NS)      cpa_wait0();
        else if (s + 2 >= NS) cpa_wait1();
        else                  cpa_wait2();
        __syncthreads();
        if (s + 3 < NS) GPREF(s + 3);

        const uint32_t stgA = stA0 + (s % NSTG) * (ASLAB * 2);
        const uint32_t stgB = stB0 + (s % NSTG) * (ASLAB * 2);
        // batch ALL fragments for the stage (8 ldmatrix.x4), then 16 MMAs
        uint32_t afr[2][2][4];
        uint32_t bfr[2][2][4];
#pragma unroll
        for (int ks = 0; ks < 2; ks++) {
            const uint32_t kb = ks * 32;
#pragma unroll
            for (int mt = 0; mt < 2; mt++) ldsm_x4(afr[ks][mt], stgA + kb + aoff[mt]);
#pragma unroll
            for (int p = 0; p < 2; p++)  ldsm_x4(bfr[ks][p], stgB + kb + boff[p]);
        }
#pragma unroll
        for (int ks = 0; ks < 2; ks++)
#pragma unroll
            for (int mt = 0; mt < 2; mt++)
#pragma unroll
                for (int p = 0; p < 2; p++) {
                    mma_bf16(acc[mt][2*p  ], afr[ks][mt], &bfr[ks][p][0]);
                    mma_bf16(acc[mt][2*p+1], afr[ks][mt], &bfr[ks][p][2]);
                }
    }

    // epilogue
#pragma unroll
    for (int mt = 0; mt < 2; mt++) {
#pragma unroll
        for (int half = 0; half < 2; half++) {
            const int grow = brow + wm + 16 * mt + grp + 8 * half;
            const float* rrow = (MODE == 1) ? (resid + (size_t)grow * N + bcol) : nullptr;
#pragma unroll
            for (int nt = 0; nt < 4; nt++) {
                const int col = wn + 8 * nt + 2 * tig;
                float ox = acc[mt][nt][2 * half + 0] + bias[bcol + col];
                float oy = acc[mt][nt][2 * half + 1] + bias[bcol + col + 1];
                if (MODE == 1) {
                    const float2 rv = *(const float2*)(rrow + col);
                    ox += rv.x; oy += rv.y;
                    float2 o; o.x = ox; o.y = oy;
                    *(float2*)((float*)Cout + (size_t)grow * N + bcol + col) = o;
                } else {
                    if (MODE == 2) { ox = fmaxf(ox, 0.f); oy = fmaxf(oy, 0.f); }
                    ((uint32_t*)Cout)[((size_t)grow * N + bcol + col) >> 1] = bfpack(ox, oy);
                }
            }
        }
    }
}

// ============ sliding-window flash attention, full bf16 mma ==================
// Q tile 64 rows, 4 warps (16 rows each). P stays in registers (C->A repack).
// K B-frags: plain ldmatrix; V B-frags: ldmatrix.trans. Stride 72 conflict-free.
#define QK_STR 72
#define KVBUF  (64 * QK_STR)     // uint16 elems per buffer

__global__ __launch_bounds__(128)
void attn_bf(const uint16_t* __restrict__ qkv, uint32_t* __restrict__ ctxbf,
             const int* __restrict__ wptr)
{
    __shared__ __align__(16) uint16_t Qs[KVBUF];
    __shared__ __align__(16) uint16_t Ks[2][KVBUF];
    __shared__ __align__(16) uint16_t Vs[2][KVBUF];

    int w = *wptr;
    if (w < 0 || w > 1000000) w = (int)__int_as_float((unsigned)w);

    const int t    = threadIdx.x;
    const int warp = t >> 5;
    const int lane = t & 31;
    const int grp  = lane >> 2;
    const int tig  = lane & 3;
    const int wm   = warp * 16;
    const int q0   = blockIdx.x * 64;
    const int h    = blockIdx.y;
    const int b    = blockIdx.z;

    const uint32_t qsb = (uint32_t)__cvta_generic_to_shared(Qs);
    const uint32_t ksb = (uint32_t)__cvta_generic_to_shared(Ks);
    const uint32_t vsb = (uint32_t)__cvta_generic_to_shared(Vs);

    int j0s = q0 - w; if (j0s < 0) j0s = 0; j0s &= ~63;
    int jend = q0 + 64 + w; if (jend > SS) jend = SS;
    const int ntl = (jend - j0s + 63) >> 6;

    const int pr  = t & 63;
    const int isV = t >> 6;
#define APREF(ti, buf) do { \
        const int _jr = j0s + (ti) * 64 + pr; \
        const int _sz = (_jr < SS) ? 16 : 0; \
        const int _jc = (_jr < SS) ? _jr : (SS - 1); \
        const uint16_t* _src = qkv + ((size_t)(b * SS + _jc)) * 1536 + 512 + isV * 512 + h * 64; \
        const uint32_t _dst = (isV ? vsb : ksb) + (buf) * (KVBUF * 2) + pr * (QK_STR * 2); \
        _Pragma("unroll") \
        for (int _ci = 0; _ci < 8; _ci++) cpa16z(_dst + 16 * _ci, _src + 8 * _ci, _sz); \
        cpa_commit(); \
    } while (0)

    // stage Q (cp.async) + start tile-0 prefetch
    {
        const int qr = t >> 1, qh = (t & 1) * 32;
        const uint16_t* qp = qkv + ((size_t)(b * SS + q0 + qr)) * 1536 + h * 64 + qh;
        const uint32_t qd = qsb + (qr * QK_STR + qh) * 2;
#pragma unroll
        for (int i = 0; i < 4; i++) cpa16(qd + 16 * i, qp + 8 * i);
    }
    APREF(0, 0);
    cpa_wait0();
    __syncthreads();

    // Q A-fragments (registers, reused across all tiles)
    uint32_t aq[4][4];
#pragma unroll
    for (int kt = 0; kt < 4; kt++)
        ldsm_x4(aq[kt], qsb + ((wm + (lane & 15)) * QK_STR + kt * 16 + ((lane >> 4) & 1) * 8) * 2);

    uint32_t koff[4], voff[4];
#pragma unroll
    for (int p = 0; p < 4; p++) {
        koff[p] = ((16 * p + (lane & 7) + ((lane >> 4) & 1) * 8) * QK_STR
                   + ((lane >> 3) & 1) * 8) * 2;
        voff[p] = (((lane & 7) + ((lane >> 3) & 1) * 8) * QK_STR
                   + p * 16 + ((lane >> 4) & 1) * 8) * 2;
    }

    float oc[8][4];
#pragma unroll
    for (int nt = 0; nt < 8; nt++) { oc[nt][0]=0.f; oc[nt][1]=0.f; oc[nt][2]=0.f; oc[nt][3]=0.f; }
    float m0 = -1e30f, m1 = -1e30f, l0 = 0.f, l1 = 0.f;
    const int qg0 = q0 + wm + grp, qg1 = qg0 + 8;

    for (int ti = 0; ti < ntl; ti++) {
        if (ti + 1 < ntl) { APREF(ti + 1, (ti + 1) & 1); cpa_wait1(); }
        else              { cpa_wait0(); }
        __syncthreads();

        const uint32_t kbase = ksb + (ti & 1) * (KVBUF * 2);
        const uint32_t vbase = vsb + (ti & 1) * (KVBUF * 2);
        const int j0 = j0s + ti * 64;

        // ---- S = Q @ K^T (bf16) ------------------------------------------
        float sc[8][4];
#pragma unroll
        for (int nt = 0; nt < 8; nt++) { sc[nt][0]=0.f; sc[nt][1]=0.f; sc[nt][2]=0.f; sc[nt][3]=0.f; }
#pragma unroll
        for (int kd = 0; kd < 4; kd++) {
#pragma unroll
            for (int p = 0; p < 4; p++) {
                uint32_t bq[4];
                ldsm_x4(bq, kbase + koff[p] + kd * 32);
                mma_bf16(sc[2*p  ], aq[kd], &bq[0]);
                mma_bf16(sc[2*p+1], aq[kd], &bq[2]);
            }
        }

        // ---- scale + mask + online softmax -------------------------------
        float tm0 = -1e30f, tm1 = -1e30f;
#pragma unroll
        for (int nt = 0; nt < 8; nt++) {
            sc[nt][0] *= 0.125f; sc[nt][1] *= 0.125f;
            sc[nt][2] *= 0.125f; sc[nt][3] *= 0.125f;
            const int ja = j0 + 8 * nt + 2 * tig;
            const int jb = ja + 1;
            if (ja >= SS || abs(qg0 - ja) > w) sc[nt][0] = -1e30f;
            if (jb >= SS || abs(qg0 - jb) > w) sc[nt][1] = -1e30f;
            if (ja >= SS || abs(qg1 - ja) > w) sc[nt][2] = -1e30f;
            if (jb >= SS || abs(qg1 - jb) > w) sc[nt][3] = -1e30f;
            tm0 = fmaxf(tm0, fmaxf(sc[nt][0], sc[nt][1]));
            tm1 = fmaxf(tm1, fmaxf(sc[nt][2], sc[nt][3]));
        }
        tm0 = fmaxf(tm0, __shfl_xor_sync(0xffffffffu, tm0, 1));
        tm0 = fmaxf(tm0, __shfl_xor_sync(0xffffffffu, tm0, 2));
        tm1 = fmaxf(tm1, __shfl_xor_sync(0xffffffffu, tm1, 1));
        tm1 = fmaxf(tm1, __shfl_xor_sync(0xffffffffu, tm1, 2));
        const float mn0 = fmaxf(m0, tm0), mn1 = fmaxf(m1, tm1);
        const float cf0 = __expf(m0 - mn0), cf1 = __expf(m1 - mn1);
        l0 *= cf0; l1 *= cf1;
#pragma unroll
        for (int nt = 0; nt < 8; nt++) {
            oc[nt][0] *= cf0; oc[nt][1] *= cf0;
            oc[nt][2] *= cf1; oc[nt][3] *= cf1;
        }
        float rs0 = 0.f, rs1 = 0.f;
#pragma unroll
        for (int nt = 0; nt < 8; nt++) {
            sc[nt][0] = __expf(sc[nt][0] - mn0);
            sc[nt][1] = __expf(sc[nt][1] - mn0);
            sc[nt][2] = __expf(sc[nt][2] - mn1);
            sc[nt][3] = __expf(sc[nt][3] - mn1);
            rs0 += sc[nt][0] + sc[nt][1];
            rs1 += sc[nt][2] + sc[nt][3];
        }
        rs0 += __shfl_xor_sync(0xffffffffu, rs0, 1);
        rs0 += __shfl_xor_sync(0xffffffffu, rs0, 2);
        rs1 += __shfl_xor_sync(0xffffffffu, rs1, 1);
        rs1 += __shfl_xor_sync(0xffffffffu, rs1, 2);
        l0 += rs0; l1 += rs1;
        m0 = mn0; m1 = mn1;

        // ---- P C-frags -> A-frags entirely in registers ------------------
        uint32_t ap[4][4];
#pragma unroll
        for (int jt = 0; jt < 4; jt++) {
            ap[jt][0] = bfpack(sc[2*jt  ][0], sc[2*jt  ][1]);
            ap[jt][1] = bfpack(sc[2*jt  ][2], sc[2*jt  ][3]);
            ap[jt][2] = bfpack(sc[2*jt+1][0], sc[2*jt+1][1]);
            ap[jt][3] = bfpack(sc[2*jt+1][2], sc[2*jt+1][3]);
        }

        // ---- O += P @ V (V^T via ldmatrix.trans) -------------------------
#pragma unroll
        for (int jt = 0; jt < 4; jt++) {
            const uint32_t jb2 = vbase + jt * (16 * QK_STR * 2);
#pragma unroll
            for (int p = 0; p < 4; p++) {
                uint32_t bv[4];
                ldsm_x4t(bv, jb2 + voff[p]);
                mma_bf16(oc[2*p  ], ap[jt], &bv[0]);
                mma_bf16(oc[2*p+1], ap[jt], &bv[2]);
            }
        }
        __syncthreads();   // done with this K/V buffer before refill
    }

    const float inv0 = 1.f / l0, inv1 = 1.f / l1;
    uint32_t* c0p = ctxbf + (((size_t)(b * SS + qg0)) * DD + h * 64) / 2;
    uint32_t* c1p = ctxbf + (((size_t)(b * SS + qg1)) * DD + h * 64) / 2;
#pragma unroll
    for (int nt = 0; nt < 8; nt++) {
        const int d = 8 * nt + 2 * tig;
        c0p[d >> 1] = bfpack(oc[nt][0] * inv0, oc[nt][1] * inv0);
        c1p[d >> 1] = bfpack(oc[nt][2] * inv1, oc[nt][3] * inv1);
    }
}

// ---------------- LayerNorm (one block per row, D=512) ----------------------
__global__ __launch_bounds__(128)
void ln_kernel(const float* __restrict__ in, const float* __restrict__ g,
               const float* __restrict__ b, float* __restrict__ out,
               uint32_t* __restrict__ outbf)
{
    __shared__ float red[4];
    const int row = blockIdx.x;
    const int t = threadIdx.x;
    float4 v = ((const float4*)(in + (size_t)row * DD))[t];

    float s = v.x + v.y + v.z + v.w;
#pragma unroll
    for (int o1 = 16; o1; o1 >>= 1) s += __shfl_xor_sync(0xffffffffu, s, o1);
    if ((t & 31) == 0) red[t >> 5] = s;
    __syncthreads();
    const float mean = (red[0] + red[1] + red[2] + red[3]) * (1.f / 512.f);

    const float dx0 = v.x - mean, dx1 = v.y - mean, dx2 = v.z - mean, dx3 = v.w - mean;
    float sq = dx0*dx0 + dx1*dx1 + dx2*dx2 + dx3*dx3;
#pragma unroll
    for (int o1 = 16; o1; o1 >>= 1) sq += __shfl_xor_sync(0xffffffffu, sq, o1);
    __syncthreads();
    if ((t & 31) == 0) red[t >> 5] = sq;
    __syncthreads();
    const float var = (red[0] + red[1] + red[2] + red[3]) * (1.f / 512.f);
    const float rs = rsqrtf(var + 1e-5f);

    float4 gv = ((const float4*)g)[t];
    float4 bv = ((const float4*)b)[t];
    float4 ov;
    ov.x = dx0 * rs * gv.x + bv.x;
    ov.y = dx1 * rs * gv.y + bv.y;
    ov.z = dx2 * rs * gv.z + bv.z;
    ov.w = dx3 * rs * gv.w + bv.w;
    ((float4*)(out + (size_t)row * DD))[t] = ov;
    if (outbf) {
        uint2 p;
        p.x = bfpack(ov.x, ov.y);
        p.y = bfpack(ov.z, ov.w);
        ((uint2*)(outbf + (size_t)row * DD / 2))[t] = p;
    }
}

// ---------------- launch ----------------------------------------------------
extern "C" void kernel_launch(void* const* d_in, const int* in_sizes, int n_in,
                              void* d_out, int out_size)
{
    const float* x     = (const float*)d_in[0];
    const float* w_in  = (const float*)d_in[1];
    const float* b_in  = (const float*)d_in[2];
    const float* w_out = (const float*)d_in[3];
    const float* b_out = (const float*)d_in[4];
    const float* ln1g  = (const float*)d_in[5];
    const float* ln1b  = (const float*)d_in[6];
    const float* ln2g  = (const float*)d_in[7];
    const float* ln2b  = (const float*)d_in[8];
    const float* w1    = (const float*)d_in[9];
    const float* b1    = (const float*)d_in[10];
    const float* w2    = (const float*)d_in[11];
    const float* b2    = (const float*)d_in[12];
    const int*   wnd   = (const int*)d_in[13];

    float *r1, *hbuf;
    uint16_t* qkvbf;
    uint32_t *xbf, *ctxbf, *hbf, *midbf, *winbf, *woutbf, *w1bf, *w2bf;
    cudaGetSymbolAddress((void**)&qkvbf,  g_qkvbf);
    cudaGetSymbolAddress((void**)&r1,     g_r1);
    cudaGetSymbolAddress((void**)&hbuf,   g_h);
    cudaGetSymbolAddress((void**)&xbf,    g_xbf);
    cudaGetSymbolAddress((void**)&ctxbf,  g_ctxbf);
    cudaGetSymbolAddress((void**)&hbf,    g_hbf);
    cudaGetSymbolAddress((void**)&midbf,  g_midbf);
    cudaGetSymbolAddress((void**)&winbf,  g_winbf);
    cudaGetSymbolAddress((void**)&woutbf, g_woutbf);
    cudaGetSymbolAddress((void**)&w1bf,   g_w1bf);
    cudaGetSymbolAddress((void**)&w2bf,   g_w2bf);

    // 0) fused bf16 conversions (x + all weights)
    cvtbf_all<<<CVT_TOT / 256, 256>>>(x, w_in, w_out, w1, w2,
                                      xbf, winbf, woutbf, w1bf, w2bf);
    // 1) fused QKV projection -> bf16 qkv   (24 x 128 = 3072 CTAs)
    gemm_bf<3><<<dim3(24, 128), 128>>>(xbf, winbf, b_in, nullptr, qkvbf, MM, 1536, DD);
    // 2) sliding-window flash attention (bf16) -> bf16 ctx
    attn_bf<<<dim3(SS / 64, HH, BB), 128>>>(qkvbf, ctxbf, wnd);
    // 3) out_proj + residual(x) -> fp32 r1  (8 x 128 = 1024 CTAs)
    gemm_bf<1><<<dim3(8, 128), 128>>>(ctxbf, woutbf, b_out, x, r1, MM, DD, DD);
    // 4) LN1 -> fp32 h + bf16 shadow
    ln_kernel<<<MM, 128>>>(r1, ln1g, ln1b, hbuf, hbf);
    // 5) MLP fc1 + relu -> bf16 mid
    gemm_bf<2><<<dim3(8, 128), 128>>>(hbf, w1bf, b1, nullptr, midbf, MM, DD, DD);
    // 6) MLP fc2 + residual(h) -> fp32 r1
    gemm_bf<1><<<dim3(8, 128), 128>>>(midbf, w2bf, b2, hbuf, r1, MM, DD, DD);
    // 7) LN2 -> output
    ln_kernel<<<MM, 128>>>(r1, ln2g, ln2b, (float*)d_out, nullptr);
}